// round 13
// baseline (speedup 1.0000x reference)
#include <cuda_runtime.h>
#include <cuda_bf16.h>
#include <math.h>
#include <stdint.h>

#define BB 4
#define TT 256
#define UU 64
#define UP 65          // U+1
#define DJ 512
#define VV 1024
#define MTILE 128      // lattice rows per joint CTA
#define A_BYTES (MTILE*DJ*2)     // 131072
#define BT_BYTES (256*128)       // 32768: 256n x 64k bf16, 128B rows (SW128 atom)
#define NBUF 3
#define NTILES 32                // 4 nc x 8 ktile
#define JTHREADS 512

// ---------------- scratch ----------------
__device__ float g_enc_h[BB*TT*DJ];
__device__ float g_dec_h[BB*UP*DJ];
__device__ float g_blank[BB*TT*UP];
__device__ float g_emit [BB*TT*UU];
__device__ float g_final[BB];
__device__ __nv_bfloat16 g_wp[VV*DJ];   // W_proj bf16 [V][K] row-major

// ---------------- helpers ----------------
__device__ __forceinline__ uint32_t smem_u32(const void* p) {
    uint32_t a;
    asm("{ .reg .u64 t; cvta.to.shared.u64 t, %1; cvt.u32.u64 %0, t; }" : "=r"(a) : "l"(p));
    return a;
}
__device__ __forceinline__ float tanh_fast(float x) {
    float r; asm("tanh.approx.f32 %0, %1;" : "=f"(r) : "f"(x)); return r;
}
__device__ __forceinline__ uint32_t pack_bf16x2(float lo, float hi) {
    uint32_t r; asm("cvt.rn.bf16x2.f32 %0, %1, %2;" : "=r"(r) : "f"(hi), "f"(lo)); return r;
}
__device__ __forceinline__ void cp_async16(uint32_t dst, const void* src) {
    asm volatile("cp.async.cg.shared.global [%0], [%1], 16;\n" :: "r"(dst), "l"(src) : "memory");
}
__device__ __forceinline__ void ldsm_x4(uint32_t (&r)[4], uint32_t addr) {
    asm volatile("ldmatrix.sync.aligned.m8n8.x4.shared.b16 {%0,%1,%2,%3}, [%4];"
                 : "=r"(r[0]), "=r"(r[1]), "=r"(r[2]), "=r"(r[3]) : "r"(addr));
}
__device__ __forceinline__ void mma_bf16(float (&c)[4], const uint32_t (&a)[4],
                                         uint32_t b0, uint32_t b1) {
    asm volatile(
        "mma.sync.aligned.m16n8k16.row.col.f32.bf16.bf16.f32 "
        "{%0,%1,%2,%3}, {%4,%5,%6,%7}, {%8,%9}, {%0,%1,%2,%3};"
        : "+f"(c[0]), "+f"(c[1]), "+f"(c[2]), "+f"(c[3])
        : "r"(a[0]), "r"(a[1]), "r"(a[2]), "r"(a[3]), "r"(b0), "r"(b1));
}

// =====================================================================
// K1: projections (z=0: enc, z=1: dec) + W_proj convert (z=2) fused
// =====================================================================
__global__ void __launch_bounds__(256) gemm_bias_kernel(
    const float* __restrict__ A0, const float* __restrict__ W0,
    const float* __restrict__ b0, float* __restrict__ C0, int M0,
    const float* __restrict__ A1, const float* __restrict__ W1,
    const float* __restrict__ b1, float* __restrict__ C1, int M1,
    const float* __restrict__ Wp)
{
    if (blockIdx.z == 2) {
        int idx = (blockIdx.x * 8 + blockIdx.y) * 256 + threadIdx.x;
        g_wp[idx] = __float2bfloat16(Wp[idx]);
        return;
    }
    const float* A; const float* W; const float* bias; float* C; int M;
    if (blockIdx.z == 0) { A = A0; W = W0; bias = b0; C = C0; M = M0; }
    else                 { A = A1; W = W1; bias = b1; C = C1; M = M1; }
    const int m0 = blockIdx.x * 64;
    if (m0 >= M) return;
    const int n0 = blockIdx.y * 64;
    const int K = 512, N = DJ;

    __shared__ float As[16][64];
    __shared__ float Ws[16][64];
    const int tid = threadIdx.x;
    const int tm = tid >> 4, tn = tid & 15;

    float acc[4][4];
#pragma unroll
    for (int i = 0; i < 4; i++)
#pragma unroll
        for (int j = 0; j < 4; j++) acc[i][j] = 0.f;

    for (int k0 = 0; k0 < K; k0 += 16) {
        __syncthreads();
#pragma unroll
        for (int i = 0; i < 4; i++) {
            int q = tid + i * 256;
            int mm = q >> 4, kk = q & 15;
            int gm = m0 + mm;
            As[kk][mm] = (gm < M) ? A[(size_t)gm * K + k0 + kk] : 0.f;
            int gn = n0 + mm;
            Ws[kk][mm] = W[(size_t)gn * K + k0 + kk];
        }
        __syncthreads();
#pragma unroll
        for (int kk = 0; kk < 16; kk++) {
            float a[4], w[4];
#pragma unroll
            for (int i = 0; i < 4; i++) a[i] = As[kk][tm * 4 + i];
#pragma unroll
            for (int j = 0; j < 4; j++) w[j] = Ws[kk][tn * 4 + j];
#pragma unroll
            for (int i = 0; i < 4; i++)
#pragma unroll
                for (int j = 0; j < 4; j++) acc[i][j] = fmaf(a[i], w[j], acc[i][j]);
        }
    }
#pragma unroll
    for (int i = 0; i < 4; i++) {
        int gm = m0 + tm * 4 + i;
        if (gm < M) {
#pragma unroll
            for (int j = 0; j < 4; j++) {
                int gn = n0 + tn * 4 + j;
                C[(size_t)gm * N + gn] = acc[i][j] + bias[gn];
            }
        }
    }
}

// =====================================================================
// K3: mma.sync bf16 joint GEMM + fused log-softmax (R6 config)
// =====================================================================
__device__ __forceinline__ void load_b_tile(int bt, uint32_t b_base, int tid) {
    uint32_t buf = b_base + (uint32_t)(bt % NBUF) * BT_BYTES;
    const int nc = bt >> 3, ktl = bt & 7;
    const int n = tid >> 1;                 // 256 rows, 2 threads/row
    const int c0 = (tid & 1) * 4;           // 4 x 16B per thread
    const __nv_bfloat16* src = g_wp + ((size_t)(nc * 256 + n) * DJ + ktl * 64 + c0 * 8);
    const uint32_t row = buf + (uint32_t)n * 128u;
    const uint32_t sw = (uint32_t)(n & 7);
#pragma unroll
    for (int j = 0; j < 4; j++) {
        uint32_t c = (uint32_t)(c0 + j);
        cp_async16(row + ((c ^ sw) << 4), src + j * 8);
    }
    asm volatile("cp.async.commit_group;" ::: "memory");
}

__global__ void __launch_bounds__(JTHREADS, 1) joint_kernel(const int* __restrict__ targets)
{
    extern __shared__ __align__(16) char dyn[];
    __shared__ int tgtm[MTILE];

    const uint32_t base = (smem_u32(dyn) + 1023u) & ~1023u;
    const uint32_t a_base = base;
    const uint32_t b_base = base + A_BYTES;

    const int tid  = threadIdx.x;
    const int lane = tid & 31;
    const int wid  = tid >> 5;
    const int warp_m = wid & 3;     // 4 M-warps of 32 rows
    const int warp_n = wid >> 2;    // 4 N-warps of 64 cols (over 256-col chunk)
    const int g0 = blockIdx.x * MTILE;
    const unsigned FM = 0xffffffffu;

    if (tid < MTILE) {
        int g = g0 + tid;
        int b = g / (TT * UP);
        int r = g - b * (TT * UP);
        int u = r % UP;
        tgtm[tid] = (u < UU) ? targets[b * UU + u] : -1;
    }

    // ---- generate h tile into XOR-swizzled A (bf16); each thread 128 k ----
    {
        const int m = tid >> 2;
        const int kq = (tid & 3) * 128;
        int g = g0 + m;
        int b = g / (TT * UP);
        int r = g - b * (TT * UP);
        int t = r / UP, u = r - t * UP;
        const float4* er = reinterpret_cast<const float4*>(
            g_enc_h + ((size_t)(b * TT + t)) * DJ + kq);
        const float4* dr = reinterpret_cast<const float4*>(
            g_dec_h + ((size_t)(b * UP + u)) * DJ + kq);
        const uint32_t mrow = a_base + (uint32_t)m * 1024u;
        const uint32_t msw = (uint32_t)(m & 7);
#pragma unroll 4
        for (int i = 0; i < 16; i++) {
            int k = kq + i * 8;
            float4 e0 = er[i * 2], e1 = er[i * 2 + 1];
            float4 d0 = dr[i * 2], d1 = dr[i * 2 + 1];
            uint32_t p0 = pack_bf16x2(tanh_fast(e0.x * d0.x), tanh_fast(e0.y * d0.y));
            uint32_t p1 = pack_bf16x2(tanh_fast(e0.z * d0.z), tanh_fast(e0.w * d0.w));
            uint32_t p2 = pack_bf16x2(tanh_fast(e1.x * d1.x), tanh_fast(e1.y * d1.y));
            uint32_t p3 = pack_bf16x2(tanh_fast(e1.z * d1.z), tanh_fast(e1.w * d1.w));
            uint32_t c = (uint32_t)(k >> 3);
            uint32_t addr = mrow + ((c ^ msw) << 4);
            asm volatile("st.shared.v4.b32 [%0], {%1,%2,%3,%4};"
                         :: "r"(addr), "r"(p0), "r"(p1), "r"(p2), "r"(p3) : "memory");
        }
    }
    __syncthreads();

    // ---- prologue: prefetch B tiles 0,1 ----
    load_b_tile(0, b_base, tid);
    load_b_tile(1, b_base, tid);

    // ---- per-lane ldmatrix addressing ----
    const int rowA = warp_m * 32 + (lane & 15);
    const uint32_t a_lane = a_base + (uint32_t)rowA * 1024u;
    const uint32_t swzA = (uint32_t)(rowA & 7);
    const uint32_t cbaseA = (uint32_t)(lane >> 4);
    const int n_row_base = warp_n * 64 + ((lane >> 4) << 3) + (lane & 7);
    const uint32_t kh = (uint32_t)((lane >> 3) & 1);
    const uint32_t swzB = (uint32_t)(lane & 7);
    uint32_t rowoffB[4];
#pragma unroll
    for (int p = 0; p < 4; p++) rowoffB[p] = (uint32_t)(n_row_base + p * 16) * 128u;

    // ---- per-row epilogue state ----
    float sm[4], blankv[4], tgtv[4];
    int tg[4];
#pragma unroll
    for (int g = 0; g < 4; g++) {
        sm[g] = 0.f; blankv[g] = 0.f; tgtv[g] = 0.f;
        int m = warp_m * 32 + (g >> 1) * 16 + (g & 1) * 8 + (lane >> 2);
        tg[g] = tgtm[m];
    }

    float acc[2][8][4];

#pragma unroll 1
    for (int bt = 0; bt < NTILES; bt++) {
        const int ktl = bt & 7;
        if (bt < NTILES - 1) asm volatile("cp.async.wait_group 1;" ::: "memory");
        else                 asm volatile("cp.async.wait_group 0;" ::: "memory");
        __syncthreads();
        if (bt + 2 < NTILES) load_b_tile(bt + 2, b_base, tid);

        if (ktl == 0) {
#pragma unroll
            for (int mi = 0; mi < 2; mi++)
#pragma unroll
                for (int nf = 0; nf < 8; nf++)
#pragma unroll
                    for (int j = 0; j < 4; j++) acc[mi][nf][j] = 0.f;
        }

        const uint32_t bbuf = b_base + (uint32_t)(bt % NBUF) * BT_BYTES;
#pragma unroll
        for (int s = 0; s < 4; s++) {
            uint32_t a0[4], a1[4];
            uint32_t cA = (uint32_t)(ktl * 8 + s * 2) + cbaseA;
            uint32_t aaddr = a_lane + ((cA ^ swzA) << 4);
            ldsm_x4(a0, aaddr);
            ldsm_x4(a1, aaddr + 16384u);
            uint32_t b[4][4];
            uint32_t cB = ((uint32_t)(s * 2) + kh) ^ swzB;
#pragma unroll
            for (int p = 0; p < 4; p++)
                ldsm_x4(b[p], bbuf + rowoffB[p] + (cB << 4));
#pragma unroll
            for (int p = 0; p < 4; p++) {
                mma_bf16(acc[0][2 * p],     a0, b[p][0], b[p][1]);
                mma_bf16(acc[0][2 * p + 1], a0, b[p][2], b[p][3]);
                mma_bf16(acc[1][2 * p],     a1, b[p][0], b[p][1]);
                mma_bf16(acc[1][2 * p + 1], a1, b[p][2], b[p][3]);
            }
        }

        if (ktl == 7) {
            const int nc = bt >> 3;
            const int vbase = nc * 256 + warp_n * 64 + (lane & 3) * 2;
#pragma unroll
            for (int g = 0; g < 4; g++) {
                const int mi = g >> 1, hf = (g & 1) * 2;
                float ls = 0.f;
#pragma unroll
                for (int nf = 0; nf < 8; nf++)
                    ls += __expf(acc[mi][nf][hf]) + __expf(acc[mi][nf][hf + 1]);
                ls += __shfl_xor_sync(FM, ls, 1);
                ls += __shfl_xor_sync(FM, ls, 2);
                sm[g] += ls;
#pragma unroll
                for (int nf = 0; nf < 8; nf++) {
                    int v0 = vbase + nf * 8;
                    if (v0 == 0)         blankv[g] = acc[mi][nf][hf];
                    if (v0 == tg[g])     tgtv[g]   = acc[mi][nf][hf];
                    if (v0 + 1 == tg[g]) tgtv[g]   = acc[mi][nf][hf + 1];
                }
            }
        }
    }

    // gather captured values across the 4 lanes of each row group
#pragma unroll
    for (int g = 0; g < 4; g++) {
        tgtv[g]   += __shfl_xor_sync(FM, tgtv[g], 1);
        tgtv[g]   += __shfl_xor_sync(FM, tgtv[g], 2);
        blankv[g] += __shfl_xor_sync(FM, blankv[g], 1);
        blankv[g] += __shfl_xor_sync(FM, blankv[g], 2);
    }

    // reuse B buffer smem for the cross-n-warp combine
    __syncthreads();
    float* ssum   = reinterpret_cast<float*>(dyn) + ((b_base - smem_u32(dyn)) >> 2);
    float* stgtv  = ssum + 4 * MTILE;
    float* sblank = stgtv + 4 * MTILE;

    if ((lane & 3) == 0) {
#pragma unroll
        for (int g = 0; g < 4; g++) {
            int m = warp_m * 32 + (g >> 1) * 16 + (g & 1) * 8 + (lane >> 2);
            ssum[warp_n * MTILE + m]  = sm[g];
            stgtv[warp_n * MTILE + m] = tgtv[g];
            if (warp_n == 0) sblank[m] = blankv[g];
        }
    }
    __syncthreads();

    if (tid < MTILE) {
        int m = tid;
        float lse = __logf(ssum[m] + ssum[MTILE + m] + ssum[2 * MTILE + m] + ssum[3 * MTILE + m]);
        int g = g0 + m;
        int b = g / (TT * UP);
        int r = g - b * (TT * UP);
        int t = r / UP, u = r - t * UP;
        g_blank[g] = sblank[m] - lse;
        if (u < UU) {
            int h = (tgtm[m] >> 6) & 3;   // which 64-col N-warp owns target
            g_emit[(size_t)(b * TT + t) * UU + u] = stgtv[h * MTILE + m] - lse;
        }
    }
}

// =====================================================================
// K4: alpha DP — wavefront with (m,s)-pair alphas, renormalized every
// 16 diagonals (prevents s overflow). smem-staged operands.
// =====================================================================
#define DP_BL_FLOATS (TT*UP)   // 16640
#define DP_EM_FLOATS (TT*UU)   // 16384
#define DP_SMEM_BYTES ((DP_BL_FLOATS + DP_EM_FLOATS) * 4)   // 132096

__global__ void __launch_bounds__(256, 1) dp_kernel(
    const int* __restrict__ in_len, const int* __restrict__ tgt_len)
{
    extern __shared__ float sdp[];
    float* sbl = sdp;                   // [TT*UP]
    float* sem = sdp + DP_BL_FLOATS;    // [TT*UU]

    const int b = blockIdx.x;
    const int tid = threadIdx.x;

    // ---- stage blank/emit into smem (float4, coalesced) ----
    {
        const float4* gb = reinterpret_cast<const float4*>(g_blank + (size_t)b * DP_BL_FLOATS);
        float4* sb = reinterpret_cast<float4*>(sbl);
#pragma unroll
        for (int i = 0; i < DP_BL_FLOATS / 4 / 256 + 1; i++) {
            int q = tid + i * 256;
            if (q < DP_BL_FLOATS / 4) sb[q] = gb[q];
        }
        const float4* ge = reinterpret_cast<const float4*>(g_emit + (size_t)b * DP_EM_FLOATS);
        float4* se = reinterpret_cast<float4*>(sem);
#pragma unroll
        for (int i = 0; i < DP_EM_FLOATS / 4 / 256; i++) {
            int q = tid + i * 256;
            se[q] = ge[q];
        }
    }
    __syncthreads();

    if (tid >= 32) return;
    const int lane = tid;
    const int til = in_len[b];
    const int ul  = tgt_len[b];
    const int dmax = til - 1 + ul;
    const float NEG = -1e30f;
    const unsigned FM = 0xffffffffu;

    int u[3];
    float am[3], as[3];     // alpha = am + log(as)
    bool uok[3];
#pragma unroll
    for (int j = 0; j < 3; j++) {
        u[j] = lane * 3 + j;
        uok[j] = (u[j] <= UU);
        am[j] = (u[j] == 0) ? 0.f : NEG;
        as[j] = 1.f;
    }

    // operands for step d=1
    float bl[3], em[3];
#pragma unroll
    for (int j = 0; j < 3; j++) {
        int t = 1 - u[j];
        bl[j] = (t >= 1 && uok[j]) ? sbl[(t - 1) * UP + u[j]] : 0.f;
        em[j] = (t >= 0 && u[j] >= 1 && uok[j]) ? sem[t * UU + u[j] - 1] : 0.f;
    }

    float fin_m = NEG, fin_s = 1.f;

#pragma unroll 1
    for (int d = 1; d <= dmax; d++) {
        // prefetch next step's operands from smem
        float nbl[3], nem[3];
        if (d < dmax) {
#pragma unroll
            for (int j = 0; j < 3; j++) {
                int t = d + 1 - u[j];
                nbl[j] = (t >= 1 && t <= TT && uok[j]) ? sbl[(t - 1) * UP + u[j]] : 0.f;
                nem[j] = (t >= 0 && t < TT && u[j] >= 1 && uok[j]) ? sem[t * UU + u[j] - 1] : 0.f;
            }
        }

        // neighbor (u-1) pair from lane-1 slot 2 (old values)
        float mn = __shfl_up_sync(FM, am[2], 1);
        float sn = __shfl_up_sync(FM, as[2], 1);
        if (lane == 0) { mn = NEG; sn = 1.f; }

        float nm[3], ns[3];
        {
            float mx = am[0] + bl[0], my = mn + em[0];
            float mm = fmaxf(mx, my);
            nm[0] = mm;
            ns[0] = as[0] * __expf(mx - mm) + sn * __expf(my - mm);
        }
        {
            float mx = am[1] + bl[1], my = am[0] + em[1];
            float mm = fmaxf(mx, my);
            nm[1] = mm;
            ns[1] = as[1] * __expf(mx - mm) + as[0] * __expf(my - mm);
        }
        {
            float mx = am[2] + bl[2], my = am[1] + em[2];
            float mm = fmaxf(mx, my);
            nm[2] = mm;
            ns[2] = as[2] * __expf(mx - mm) + as[1] * __expf(my - mm);
        }

        const bool renorm = ((d & 15) == 0);

        // validity mask + periodic renormalization (fold log s into m)
#pragma unroll
        for (int j = 0; j < 3; j++) {
            int t = d - u[j];
            bool bad = (t < 0) || (t >= TT) || !uok[j];
            if (bad) { am[j] = NEG; as[j] = 1.f; }
            else if (renorm) { am[j] = nm[j] + __logf(ns[j]); as[j] = 1.f; }
            else { am[j] = nm[j]; as[j] = ns[j]; }
            if (d == dmax && u[j] == ul) { fin_m = am[j]; fin_s = as[j]; }
        }

        bl[0] = nbl[0]; bl[1] = nbl[1]; bl[2] = nbl[2];
        em[0] = nem[0]; em[1] = nem[1]; em[2] = nem[2];
    }

#pragma unroll
    for (int j = 0; j < 3; j++) {
        if (u[j] == ul)
            g_final[b] = fin_m + __logf(fin_s) + sbl[(til - 1) * UP + ul];
    }
}

__global__ void finalize_kernel(float* out) {
    out[0] = -0.25f * (g_final[0] + g_final[1] + g_final[2] + g_final[3]);
}

// =====================================================================
// launch
// =====================================================================
extern "C" void kernel_launch(void* const* d_in, const int* in_sizes, int n_in,
                              void* d_out, int out_size)
{
    const float* enc     = (const float*)d_in[0];
    const float* dec     = (const float*)d_in[1];
    const int*   targets = (const int*)  d_in[2];
    const int*   in_len  = (const int*)  d_in[3];
    const int*   tgt_len = (const int*)  d_in[4];
    const float* W_enc   = (const float*)d_in[5];
    const float* b_enc   = (const float*)d_in[6];
    const float* W_dec   = (const float*)d_in[7];
    const float* b_dec   = (const float*)d_in[8];
    const float* W_proj  = (const float*)d_in[9];

    void *pe = nullptr, *pd = nullptr;
    cudaGetSymbolAddress(&pe, g_enc_h);
    cudaGetSymbolAddress(&pd, g_dec_h);

    const int smem_joint = 1024 + A_BYTES + NBUF * BT_BYTES;   // 230400 B
    cudaFuncSetAttribute(joint_kernel, cudaFuncAttributeMaxDynamicSharedMemorySize, smem_joint);
    cudaFuncSetAttribute(dp_kernel, cudaFuncAttributeMaxDynamicSharedMemorySize, DP_SMEM_BYTES);

    // z=0: enc proj (x<16), z=1: dec proj (x<5), z=2: W_proj convert (256x8 blocks)
    dim3 gg(256, 8, 3);
    gemm_bias_kernel<<<gg, 256>>>(enc, W_enc, b_enc, (float*)pe, BB * TT,
                                  dec, W_dec, b_dec, (float*)pd, BB * UP,
                                  W_proj);

    joint_kernel<<<(BB * TT * UP) / MTILE, JTHREADS, smem_joint>>>(targets);

    dp_kernel<<<BB, 256, DP_SMEM_BYTES>>>(in_len, tgt_len);

    finalize_kernel<<<1, 1>>>((float*)d_out);
}

// round 14
// speedup vs baseline: 1.2744x; 1.2744x over previous
#include <cuda_runtime.h>
#include <cuda_bf16.h>
#include <math.h>
#include <stdint.h>

#define BB 4
#define TT 256
#define UU 64
#define UP 65          // U+1
#define DJ 512
#define VV 1024
#define MTILE 128      // lattice rows per joint CTA
#define A_BYTES (MTILE*DJ*2)     // 131072
#define BT_BYTES (256*128)       // 32768: 256n x 64k bf16, 128B rows (SW128 atom)
#define NBUF 3
#define NTILES 32                // 4 nc x 8 ktile
#define JTHREADS 512

// ---------------- scratch ----------------
__device__ float g_enc_h[BB*TT*DJ];
__device__ float g_dec_h[BB*UP*DJ];
__device__ float g_blank[BB*TT*UP];
__device__ float g_emit [BB*TT*UU];
__device__ float g_final[BB];
__device__ __nv_bfloat16 g_wp[VV*DJ];   // W_proj bf16 [V][K] row-major

// ---------------- helpers ----------------
__device__ __forceinline__ uint32_t smem_u32(const void* p) {
    uint32_t a;
    asm("{ .reg .u64 t; cvta.to.shared.u64 t, %1; cvt.u32.u64 %0, t; }" : "=r"(a) : "l"(p));
    return a;
}
__device__ __forceinline__ float tanh_fast(float x) {
    float r; asm("tanh.approx.f32 %0, %1;" : "=f"(r) : "f"(x)); return r;
}
__device__ __forceinline__ uint32_t pack_bf16x2(float lo, float hi) {
    uint32_t r; asm("cvt.rn.bf16x2.f32 %0, %1, %2;" : "=r"(r) : "f"(hi), "f"(lo)); return r;
}
__device__ __forceinline__ void cp_async16(uint32_t dst, const void* src) {
    asm volatile("cp.async.cg.shared.global [%0], [%1], 16;\n" :: "r"(dst), "l"(src) : "memory");
}
__device__ __forceinline__ void ldsm_x4(uint32_t (&r)[4], uint32_t addr) {
    asm volatile("ldmatrix.sync.aligned.m8n8.x4.shared.b16 {%0,%1,%2,%3}, [%4];"
                 : "=r"(r[0]), "=r"(r[1]), "=r"(r[2]), "=r"(r[3]) : "r"(addr));
}
__device__ __forceinline__ void mma_bf16(float (&c)[4], const uint32_t (&a)[4],
                                         uint32_t b0, uint32_t b1) {
    asm volatile(
        "mma.sync.aligned.m16n8k16.row.col.f32.bf16.bf16.f32 "
        "{%0,%1,%2,%3}, {%4,%5,%6,%7}, {%8,%9}, {%0,%1,%2,%3};"
        : "+f"(c[0]), "+f"(c[1]), "+f"(c[2]), "+f"(c[3])
        : "r"(a[0]), "r"(a[1]), "r"(a[2]), "r"(a[3]), "r"(b0), "r"(b1));
}

// =====================================================================
// K0: W_proj fp32 -> bf16
// =====================================================================
__global__ void convert_wp_kernel(const float* __restrict__ Wp) {
    int idx = blockIdx.x * 256 + threadIdx.x;
    g_wp[idx] = __float2bfloat16(Wp[idx]);
}

// =====================================================================
// K1: both projections in one launch (z=0: enc, z=1: dec)
// =====================================================================
__global__ void __launch_bounds__(256) gemm_bias_kernel(
    const float* __restrict__ A0, const float* __restrict__ W0,
    const float* __restrict__ b0, float* __restrict__ C0, int M0,
    const float* __restrict__ A1, const float* __restrict__ W1,
    const float* __restrict__ b1, float* __restrict__ C1, int M1)
{
    const float* A; const float* W; const float* bias; float* C; int M;
    if (blockIdx.z == 0) { A = A0; W = W0; bias = b0; C = C0; M = M0; }
    else                 { A = A1; W = W1; bias = b1; C = C1; M = M1; }
    const int m0 = blockIdx.x * 64;
    if (m0 >= M) return;
    const int n0 = blockIdx.y * 64;
    const int K = 512, N = DJ;

    __shared__ float As[16][64];
    __shared__ float Ws[16][64];
    const int tid = threadIdx.x;
    const int tm = tid >> 4, tn = tid & 15;

    float acc[4][4];
#pragma unroll
    for (int i = 0; i < 4; i++)
#pragma unroll
        for (int j = 0; j < 4; j++) acc[i][j] = 0.f;

    for (int k0 = 0; k0 < K; k0 += 16) {
        __syncthreads();
#pragma unroll
        for (int i = 0; i < 4; i++) {
            int q = tid + i * 256;
            int mm = q >> 4, kk = q & 15;
            int gm = m0 + mm;
            As[kk][mm] = (gm < M) ? A[(size_t)gm * K + k0 + kk] : 0.f;
            int gn = n0 + mm;
            Ws[kk][mm] = W[(size_t)gn * K + k0 + kk];
        }
        __syncthreads();
#pragma unroll
        for (int kk = 0; kk < 16; kk++) {
            float a[4], w[4];
#pragma unroll
            for (int i = 0; i < 4; i++) a[i] = As[kk][tm * 4 + i];
#pragma unroll
            for (int j = 0; j < 4; j++) w[j] = Ws[kk][tn * 4 + j];
#pragma unroll
            for (int i = 0; i < 4; i++)
#pragma unroll
                for (int j = 0; j < 4; j++) acc[i][j] = fmaf(a[i], w[j], acc[i][j]);
        }
    }
#pragma unroll
    for (int i = 0; i < 4; i++) {
        int gm = m0 + tm * 4 + i;
        if (gm < M) {
#pragma unroll
            for (int j = 0; j < 4; j++) {
                int gn = n0 + tn * 4 + j;
                C[(size_t)gm * N + gn] = acc[i][j] + bias[gn];
            }
        }
    }
}

// =====================================================================
// K3: mma.sync bf16 joint GEMM + fused log-softmax (R6 config)
//     + dead-tile early exit: tiles with t_min >= in_len[b] are never
//       read by the DP (cells with t>=til only influence cells with
//       larger t; u-predecessors share t), so skip them entirely.
// =====================================================================
__device__ __forceinline__ void load_b_tile(int bt, uint32_t b_base, int tid) {
    uint32_t buf = b_base + (uint32_t)(bt % NBUF) * BT_BYTES;
    const int nc = bt >> 3, ktl = bt & 7;
    const int n = tid >> 1;                 // 256 rows, 2 threads/row
    const int c0 = (tid & 1) * 4;           // 4 x 16B per thread
    const __nv_bfloat16* src = g_wp + ((size_t)(nc * 256 + n) * DJ + ktl * 64 + c0 * 8);
    const uint32_t row = buf + (uint32_t)n * 128u;
    const uint32_t sw = (uint32_t)(n & 7);
#pragma unroll
    for (int j = 0; j < 4; j++) {
        uint32_t c = (uint32_t)(c0 + j);
        cp_async16(row + ((c ^ sw) << 4), src + j * 8);
    }
    asm volatile("cp.async.commit_group;" ::: "memory");
}

__global__ void __launch_bounds__(JTHREADS, 1) joint_kernel(
    const int* __restrict__ targets, const int* __restrict__ in_len)
{
    extern __shared__ __align__(16) char dyn[];
    __shared__ int tgtm[MTILE];

    const int g0 = blockIdx.x * MTILE;
    {   // dead-tile early exit (uniform across CTA, before any barrier)
        int b = g0 / (TT * UP);
        int t_min = (g0 - b * (TT * UP)) / UP;
        if (t_min >= in_len[b]) return;
    }

    const uint32_t base = (smem_u32(dyn) + 1023u) & ~1023u;
    const uint32_t a_base = base;
    const uint32_t b_base = base + A_BYTES;

    const int tid  = threadIdx.x;
    const int lane = tid & 31;
    const int wid  = tid >> 5;
    const int warp_m = wid & 3;     // 4 M-warps of 32 rows
    const int warp_n = wid >> 2;    // 4 N-warps of 64 cols (over 256-col chunk)
    const unsigned FM = 0xffffffffu;

    if (tid < MTILE) {
        int g = g0 + tid;
        int b = g / (TT * UP);
        int r = g - b * (TT * UP);
        int u = r % UP;
        tgtm[tid] = (u < UU) ? targets[b * UU + u] : -1;
    }

    // ---- generate h tile into XOR-swizzled A (bf16); each thread 128 k ----
    {
        const int m = tid >> 2;
        const int kq = (tid & 3) * 128;
        int g = g0 + m;
        int b = g / (TT * UP);
        int r = g - b * (TT * UP);
        int t = r / UP, u = r - t * UP;
        const float4* er = reinterpret_cast<const float4*>(
            g_enc_h + ((size_t)(b * TT + t)) * DJ + kq);
        const float4* dr = reinterpret_cast<const float4*>(
            g_dec_h + ((size_t)(b * UP + u)) * DJ + kq);
        const uint32_t mrow = a_base + (uint32_t)m * 1024u;
        const uint32_t msw = (uint32_t)(m & 7);
#pragma unroll 4
        for (int i = 0; i < 16; i++) {
            int k = kq + i * 8;
            float4 e0 = er[i * 2], e1 = er[i * 2 + 1];
            float4 d0 = dr[i * 2], d1 = dr[i * 2 + 1];
            uint32_t p0 = pack_bf16x2(tanh_fast(e0.x * d0.x), tanh_fast(e0.y * d0.y));
            uint32_t p1 = pack_bf16x2(tanh_fast(e0.z * d0.z), tanh_fast(e0.w * d0.w));
            uint32_t p2 = pack_bf16x2(tanh_fast(e1.x * d1.x), tanh_fast(e1.y * d1.y));
            uint32_t p3 = pack_bf16x2(tanh_fast(e1.z * d1.z), tanh_fast(e1.w * d1.w));
            uint32_t c = (uint32_t)(k >> 3);
            uint32_t addr = mrow + ((c ^ msw) << 4);
            asm volatile("st.shared.v4.b32 [%0], {%1,%2,%3,%4};"
                         :: "r"(addr), "r"(p0), "r"(p1), "r"(p2), "r"(p3) : "memory");
        }
    }
    __syncthreads();

    // ---- prologue: prefetch B tiles 0,1 ----
    load_b_tile(0, b_base, tid);
    load_b_tile(1, b_base, tid);

    // ---- per-lane ldmatrix addressing ----
    const int rowA = warp_m * 32 + (lane & 15);
    const uint32_t a_lane = a_base + (uint32_t)rowA * 1024u;
    const uint32_t swzA = (uint32_t)(rowA & 7);
    const uint32_t cbaseA = (uint32_t)(lane >> 4);
    const int n_row_base = warp_n * 64 + ((lane >> 4) << 3) + (lane & 7);
    const uint32_t kh = (uint32_t)((lane >> 3) & 1);
    const uint32_t swzB = (uint32_t)(lane & 7);
    uint32_t rowoffB[4];
#pragma unroll
    for (int p = 0; p < 4; p++) rowoffB[p] = (uint32_t)(n_row_base + p * 16) * 128u;

    // ---- per-row epilogue state ----
    float sm[4], blankv[4], tgtv[4];
    int tg[4];
#pragma unroll
    for (int g = 0; g < 4; g++) {
        sm[g] = 0.f; blankv[g] = 0.f; tgtv[g] = 0.f;
        int m = warp_m * 32 + (g >> 1) * 16 + (g & 1) * 8 + (lane >> 2);
        tg[g] = tgtm[m];
    }

    float acc[2][8][4];

#pragma unroll 1
    for (int bt = 0; bt < NTILES; bt++) {
        const int ktl = bt & 7;
        if (bt < NTILES - 1) asm volatile("cp.async.wait_group 1;" ::: "memory");
        else                 asm volatile("cp.async.wait_group 0;" ::: "memory");
        __syncthreads();
        if (bt + 2 < NTILES) load_b_tile(bt + 2, b_base, tid);

        if (ktl == 0) {
#pragma unroll
            for (int mi = 0; mi < 2; mi++)
#pragma unroll
                for (int nf = 0; nf < 8; nf++)
#pragma unroll
                    for (int j = 0; j < 4; j++) acc[mi][nf][j] = 0.f;
        }

        const uint32_t bbuf = b_base + (uint32_t)(bt % NBUF) * BT_BYTES;
#pragma unroll
        for (int s = 0; s < 4; s++) {
            uint32_t a0[4], a1[4];
            uint32_t cA = (uint32_t)(ktl * 8 + s * 2) + cbaseA;
            uint32_t aaddr = a_lane + ((cA ^ swzA) << 4);
            ldsm_x4(a0, aaddr);
            ldsm_x4(a1, aaddr + 16384u);
            uint32_t b[4][4];
            uint32_t cB = ((uint32_t)(s * 2) + kh) ^ swzB;
#pragma unroll
            for (int p = 0; p < 4; p++)
                ldsm_x4(b[p], bbuf + rowoffB[p] + (cB << 4));
#pragma unroll
            for (int p = 0; p < 4; p++) {
                mma_bf16(acc[0][2 * p],     a0, b[p][0], b[p][1]);
                mma_bf16(acc[0][2 * p + 1], a0, b[p][2], b[p][3]);
                mma_bf16(acc[1][2 * p],     a1, b[p][0], b[p][1]);
                mma_bf16(acc[1][2 * p + 1], a1, b[p][2], b[p][3]);
            }
        }

        if (ktl == 7) {
            const int nc = bt >> 3;
            const int vbase = nc * 256 + warp_n * 64 + (lane & 3) * 2;
#pragma unroll
            for (int g = 0; g < 4; g++) {
                const int mi = g >> 1, hf = (g & 1) * 2;
                float ls = 0.f;
#pragma unroll
                for (int nf = 0; nf < 8; nf++)
                    ls += __expf(acc[mi][nf][hf]) + __expf(acc[mi][nf][hf + 1]);
                ls += __shfl_xor_sync(FM, ls, 1);
                ls += __shfl_xor_sync(FM, ls, 2);
                sm[g] += ls;
#pragma unroll
                for (int nf = 0; nf < 8; nf++) {
                    int v0 = vbase + nf * 8;
                    if (v0 == 0)         blankv[g] = acc[mi][nf][hf];
                    if (v0 == tg[g])     tgtv[g]   = acc[mi][nf][hf];
                    if (v0 + 1 == tg[g]) tgtv[g]   = acc[mi][nf][hf + 1];
                }
            }
        }
    }

    // gather captured values across the 4 lanes of each row group
#pragma unroll
    for (int g = 0; g < 4; g++) {
        tgtv[g]   += __shfl_xor_sync(FM, tgtv[g], 1);
        tgtv[g]   += __shfl_xor_sync(FM, tgtv[g], 2);
        blankv[g] += __shfl_xor_sync(FM, blankv[g], 1);
        blankv[g] += __shfl_xor_sync(FM, blankv[g], 2);
    }

    // reuse B buffer smem for the cross-n-warp combine
    __syncthreads();
    float* ssum   = reinterpret_cast<float*>(dyn) + ((b_base - smem_u32(dyn)) >> 2);
    float* stgtv  = ssum + 4 * MTILE;
    float* sblank = stgtv + 4 * MTILE;

    if ((lane & 3) == 0) {
#pragma unroll
        for (int g = 0; g < 4; g++) {
            int m = warp_m * 32 + (g >> 1) * 16 + (g & 1) * 8 + (lane >> 2);
            ssum[warp_n * MTILE + m]  = sm[g];
            stgtv[warp_n * MTILE + m] = tgtv[g];
            if (warp_n == 0) sblank[m] = blankv[g];
        }
    }
    __syncthreads();

    if (tid < MTILE) {
        int m = tid;
        float lse = __logf(ssum[m] + ssum[MTILE + m] + ssum[2 * MTILE + m] + ssum[3 * MTILE + m]);
        int g = g0 + m;
        int b = g / (TT * UP);
        int r = g - b * (TT * UP);
        int t = r / UP, u = r - t * UP;
        g_blank[g] = sblank[m] - lse;
        if (u < UU) {
            int h = (tgtm[m] >> 6) & 3;   // which 64-col N-warp owns target
            g_emit[(size_t)(b * TT + t) * UU + u] = stgtv[h * MTILE + m] - lse;
        }
    }
}

// =====================================================================
// K4: alpha DP — anti-diagonal wavefront with smem-staged operands.
// 256 threads: all warps cooperatively stage blank/emit, warp 0 runs DP.
// =====================================================================
__device__ __forceinline__ float lse2(float a, float b) {
    float m = fmaxf(a, b);
    float n = fminf(a, b);
    return m + __logf(1.f + __expf(n - m));
}

#define DP_BL_FLOATS (TT*UP)   // 16640
#define DP_EM_FLOATS (TT*UU)   // 16384
#define DP_SMEM_BYTES ((DP_BL_FLOATS + DP_EM_FLOATS) * 4)   // 132096

__global__ void __launch_bounds__(256, 1) dp_kernel(
    const int* __restrict__ in_len, const int* __restrict__ tgt_len)
{
    extern __shared__ float sdp[];
    float* sbl = sdp;                   // [TT*UP]
    float* sem = sdp + DP_BL_FLOATS;    // [TT*UU]

    const int b = blockIdx.x;
    const int tid = threadIdx.x;

    // ---- stage blank/emit into smem (float4, coalesced) ----
    {
        const float4* gb = reinterpret_cast<const float4*>(g_blank + (size_t)b * DP_BL_FLOATS);
        float4* sb = reinterpret_cast<float4*>(sbl);
#pragma unroll
        for (int i = 0; i < DP_BL_FLOATS / 4 / 256 + 1; i++) {
            int q = tid + i * 256;
            if (q < DP_BL_FLOATS / 4) sb[q] = gb[q];
        }
        const float4* ge = reinterpret_cast<const float4*>(g_emit + (size_t)b * DP_EM_FLOATS);
        float4* se = reinterpret_cast<float4*>(sem);
#pragma unroll
        for (int i = 0; i < DP_EM_FLOATS / 4 / 256; i++) {
            int q = tid + i * 256;
            se[q] = ge[q];
        }
    }
    __syncthreads();

    if (tid >= 32) return;
    const int lane = tid;
    const int til = in_len[b];
    const int ul  = tgt_len[b];
    const int dmax = til - 1 + ul;
    const float NEG = -1e30f;
    const unsigned FM = 0xffffffffu;

    int u[3];
    float al[3];
    bool uok[3];
#pragma unroll
    for (int j = 0; j < 3; j++) {
        u[j] = lane * 3 + j;
        uok[j] = (u[j] <= UU);
        al[j] = (u[j] == 0) ? 0.f : NEG;
    }

    // operands for step d=1
    float bl[3], em[3];
#pragma unroll
    for (int j = 0; j < 3; j++) {
        int t = 1 - u[j];
        bl[j] = (t >= 1 && uok[j]) ? sbl[(t - 1) * UP + u[j]] : 0.f;
        em[j] = (t >= 0 && u[j] >= 1 && uok[j]) ? sem[t * UU + u[j] - 1] : 0.f;
    }

    float fin = NEG;

#pragma unroll 1
    for (int d = 1; d <= dmax; d++) {
        // prefetch next step's operands from smem
        float nbl[3], nem[3];
        if (d < dmax) {
#pragma unroll
            for (int j = 0; j < 3; j++) {
                int t = d + 1 - u[j];
                nbl[j] = (t >= 1 && t <= TT && uok[j]) ? sbl[(t - 1) * UP + u[j]] : 0.f;
                nem[j] = (t >= 0 && t < TT && u[j] >= 1 && uok[j]) ? sem[t * UU + u[j] - 1] : 0.f;
            }
        }

        float nb0 = __shfl_up_sync(FM, al[2], 1);
        if (lane == 0) nb0 = NEG;

        float nw[3];
        nw[0] = lse2(al[0] + bl[0], nb0   + em[0]);
        nw[1] = lse2(al[1] + bl[1], al[0] + em[1]);
        nw[2] = lse2(al[2] + bl[2], al[1] + em[2]);

#pragma unroll
        for (int j = 0; j < 3; j++) {
            int t = d - u[j];
            if (t < 0 || t >= TT || !uok[j]) nw[j] = NEG;
            al[j] = nw[j];
            if (d == dmax && u[j] == ul) fin = nw[j];
        }

        bl[0] = nbl[0]; bl[1] = nbl[1]; bl[2] = nbl[2];
        em[0] = nem[0]; em[1] = nem[1]; em[2] = nem[2];
    }

#pragma unroll
    for (int j = 0; j < 3; j++) {
        if (u[j] == ul) g_final[b] = fin + sbl[(til - 1) * UP + ul];
    }
}

__global__ void finalize_kernel(float* out) {
    out[0] = -0.25f * (g_final[0] + g_final[1] + g_final[2] + g_final[3]);
}

// =====================================================================
// launch
// =====================================================================
extern "C" void kernel_launch(void* const* d_in, const int* in_sizes, int n_in,
                              void* d_out, int out_size)
{
    const float* enc     = (const float*)d_in[0];
    const float* dec     = (const float*)d_in[1];
    const int*   targets = (const int*)  d_in[2];
    const int*   in_len  = (const int*)  d_in[3];
    const int*   tgt_len = (const int*)  d_in[4];
    const float* W_enc   = (const float*)d_in[5];
    const float* b_enc   = (const float*)d_in[6];
    const float* W_dec   = (const float*)d_in[7];
    const float* b_dec   = (const float*)d_in[8];
    const float* W_proj  = (const float*)d_in[9];

    void *pe = nullptr, *pd = nullptr;
    cudaGetSymbolAddress(&pe, g_enc_h);
    cudaGetSymbolAddress(&pd, g_dec_h);

    const int smem_joint = 1024 + A_BYTES + NBUF * BT_BYTES;   // 230400 B
    cudaFuncSetAttribute(joint_kernel, cudaFuncAttributeMaxDynamicSharedMemorySize, smem_joint);
    cudaFuncSetAttribute(dp_kernel, cudaFuncAttributeMaxDynamicSharedMemorySize, DP_SMEM_BYTES);

    convert_wp_kernel<<<(VV * DJ) / 256, 256>>>(W_proj);

    dim3 gg((BB * TT + 63) / 64, DJ / 64, 2);
    gemm_bias_kernel<<<gg, 256>>>(enc, W_enc, b_enc, (float*)pe, BB * TT,
                                  dec, W_dec, b_dec, (float*)pd, BB * UP);

    joint_kernel<<<(BB * TT * UP) / MTILE, JTHREADS, smem_joint>>>(targets, in_len);

    dp_kernel<<<BB, 256, DP_SMEM_BYTES>>>(in_len, tgt_len);

    finalize_kernel<<<1, 1>>>((float*)d_out);
}

// round 15
// speedup vs baseline: 1.3845x; 1.0864x over previous
#include <cuda_runtime.h>
#include <cuda_bf16.h>
#include <math.h>
#include <stdint.h>

#define BB 4
#define TT 256
#define UU 64
#define UP 65          // U+1
#define DJ 512
#define VV 1024
#define MTILE 128      // lattice rows per joint CTA
#define A_BYTES (MTILE*DJ*2)     // 131072
#define BT_BYTES (256*128)       // 32768: 256n x 64k bf16, 128B rows (SW128 atom)
#define NBUF 3
#define NTILES 32                // 4 nc x 8 ktile
#define JTHREADS 512

// ---------------- scratch ----------------
__device__ float g_enc_h[BB*TT*DJ];
__device__ float g_dec_h[BB*UP*DJ];
__device__ float g_blank[BB*TT*UP];
__device__ float g_emit [BB*TT*UU];
__device__ float g_final[BB];
__device__ __nv_bfloat16 g_wp[VV*DJ];   // W_proj bf16 [V][K] row-major

// ---------------- helpers ----------------
__device__ __forceinline__ uint32_t smem_u32(const void* p) {
    uint32_t a;
    asm("{ .reg .u64 t; cvta.to.shared.u64 t, %1; cvt.u32.u64 %0, t; }" : "=r"(a) : "l"(p));
    return a;
}
__device__ __forceinline__ float tanh_fast(float x) {
    float r; asm("tanh.approx.f32 %0, %1;" : "=f"(r) : "f"(x)); return r;
}
__device__ __forceinline__ uint32_t pack_bf16x2(float lo, float hi) {
    uint32_t r; asm("cvt.rn.bf16x2.f32 %0, %1, %2;" : "=r"(r) : "f"(hi), "f"(lo)); return r;
}
__device__ __forceinline__ void cp_async16(uint32_t dst, const void* src) {
    asm volatile("cp.async.cg.shared.global [%0], [%1], 16;\n" :: "r"(dst), "l"(src) : "memory");
}
__device__ __forceinline__ void ldsm_x4(uint32_t (&r)[4], uint32_t addr) {
    asm volatile("ldmatrix.sync.aligned.m8n8.x4.shared.b16 {%0,%1,%2,%3}, [%4];"
                 : "=r"(r[0]), "=r"(r[1]), "=r"(r[2]), "=r"(r[3]) : "r"(addr));
}
__device__ __forceinline__ void mma_bf16(float (&c)[4], const uint32_t (&a)[4],
                                         uint32_t b0, uint32_t b1) {
    asm volatile(
        "mma.sync.aligned.m16n8k16.row.col.f32.bf16.bf16.f32 "
        "{%0,%1,%2,%3}, {%4,%5,%6,%7}, {%8,%9}, {%0,%1,%2,%3};"
        : "+f"(c[0]), "+f"(c[1]), "+f"(c[2]), "+f"(c[3])
        : "r"(a[0]), "r"(a[1]), "r"(a[2]), "r"(a[3]), "r"(b0), "r"(b1));
}

// =====================================================================
// K0: W_proj fp32 -> bf16
// =====================================================================
__global__ void convert_wp_kernel(const float* __restrict__ Wp) {
    int idx = blockIdx.x * 256 + threadIdx.x;
    g_wp[idx] = __float2bfloat16(Wp[idx]);
}

// =====================================================================
// K1: both projections in one launch (z=0: enc, z=1: dec)
// =====================================================================
__global__ void __launch_bounds__(256) gemm_bias_kernel(
    const float* __restrict__ A0, const float* __restrict__ W0,
    const float* __restrict__ b0, float* __restrict__ C0, int M0,
    const float* __restrict__ A1, const float* __restrict__ W1,
    const float* __restrict__ b1, float* __restrict__ C1, int M1)
{
    const float* A; const float* W; const float* bias; float* C; int M;
    if (blockIdx.z == 0) { A = A0; W = W0; bias = b0; C = C0; M = M0; }
    else                 { A = A1; W = W1; bias = b1; C = C1; M = M1; }
    const int m0 = blockIdx.x * 64;
    if (m0 >= M) return;
    const int n0 = blockIdx.y * 64;
    const int K = 512, N = DJ;

    __shared__ float As[16][64];
    __shared__ float Ws[16][64];
    const int tid = threadIdx.x;
    const int tm = tid >> 4, tn = tid & 15;

    float acc[4][4];
#pragma unroll
    for (int i = 0; i < 4; i++)
#pragma unroll
        for (int j = 0; j < 4; j++) acc[i][j] = 0.f;

    for (int k0 = 0; k0 < K; k0 += 16) {
        __syncthreads();
#pragma unroll
        for (int i = 0; i < 4; i++) {
            int q = tid + i * 256;
            int mm = q >> 4, kk = q & 15;
            int gm = m0 + mm;
            As[kk][mm] = (gm < M) ? A[(size_t)gm * K + k0 + kk] : 0.f;
            int gn = n0 + mm;
            Ws[kk][mm] = W[(size_t)gn * K + k0 + kk];
        }
        __syncthreads();
#pragma unroll
        for (int kk = 0; kk < 16; kk++) {
            float a[4], w[4];
#pragma unroll
            for (int i = 0; i < 4; i++) a[i] = As[kk][tm * 4 + i];
#pragma unroll
            for (int j = 0; j < 4; j++) w[j] = Ws[kk][tn * 4 + j];
#pragma unroll
            for (int i = 0; i < 4; i++)
#pragma unroll
                for (int j = 0; j < 4; j++) acc[i][j] = fmaf(a[i], w[j], acc[i][j]);
        }
    }
#pragma unroll
    for (int i = 0; i < 4; i++) {
        int gm = m0 + tm * 4 + i;
        if (gm < M) {
#pragma unroll
            for (int j = 0; j < 4; j++) {
                int gn = n0 + tn * 4 + j;
                C[(size_t)gm * N + gn] = acc[i][j] + bias[gn];
            }
        }
    }
}

// =====================================================================
// K3: mma.sync bf16 joint GEMM + fused log-softmax + dead-tile skip
// =====================================================================
__device__ __forceinline__ void load_b_tile(int bt, uint32_t b_base, int tid) {
    uint32_t buf = b_base + (uint32_t)(bt % NBUF) * BT_BYTES;
    const int nc = bt >> 3, ktl = bt & 7;
    const int n = tid >> 1;                 // 256 rows, 2 threads/row
    const int c0 = (tid & 1) * 4;           // 4 x 16B per thread
    const __nv_bfloat16* src = g_wp + ((size_t)(nc * 256 + n) * DJ + ktl * 64 + c0 * 8);
    const uint32_t row = buf + (uint32_t)n * 128u;
    const uint32_t sw = (uint32_t)(n & 7);
#pragma unroll
    for (int j = 0; j < 4; j++) {
        uint32_t c = (uint32_t)(c0 + j);
        cp_async16(row + ((c ^ sw) << 4), src + j * 8);
    }
    asm volatile("cp.async.commit_group;" ::: "memory");
}

__global__ void __launch_bounds__(JTHREADS, 1) joint_kernel(
    const int* __restrict__ targets, const int* __restrict__ in_len)
{
    extern __shared__ __align__(16) char dyn[];
    __shared__ int tgtm[MTILE];

    const int g0 = blockIdx.x * MTILE;
    {   // dead-tile early exit (uniform across CTA, before any barrier)
        int b = g0 / (TT * UP);
        int t_min = (g0 - b * (TT * UP)) / UP;
        if (t_min >= in_len[b]) return;
    }

    const uint32_t base = (smem_u32(dyn) + 1023u) & ~1023u;
    const uint32_t a_base = base;
    const uint32_t b_base = base + A_BYTES;

    const int tid  = threadIdx.x;
    const int lane = tid & 31;
    const int wid  = tid >> 5;
    const int warp_m = wid & 3;     // 4 M-warps of 32 rows
    const int warp_n = wid >> 2;    // 4 N-warps of 64 cols (over 256-col chunk)
    const unsigned FM = 0xffffffffu;

    if (tid < MTILE) {
        int g = g0 + tid;
        int b = g / (TT * UP);
        int r = g - b * (TT * UP);
        int u = r % UP;
        tgtm[tid] = (u < UU) ? targets[b * UU + u] : -1;
    }

    // ---- generate h tile into XOR-swizzled A (bf16); each thread 128 k ----
    {
        const int m = tid >> 2;
        const int kq = (tid & 3) * 128;
        int g = g0 + m;
        int b = g / (TT * UP);
        int r = g - b * (TT * UP);
        int t = r / UP, u = r - t * UP;
        const float4* er = reinterpret_cast<const float4*>(
            g_enc_h + ((size_t)(b * TT + t)) * DJ + kq);
        const float4* dr = reinterpret_cast<const float4*>(
            g_dec_h + ((size_t)(b * UP + u)) * DJ + kq);
        const uint32_t mrow = a_base + (uint32_t)m * 1024u;
        const uint32_t msw = (uint32_t)(m & 7);
#pragma unroll 4
        for (int i = 0; i < 16; i++) {
            int k = kq + i * 8;
            float4 e0 = er[i * 2], e1 = er[i * 2 + 1];
            float4 d0 = dr[i * 2], d1 = dr[i * 2 + 1];
            uint32_t p0 = pack_bf16x2(tanh_fast(e0.x * d0.x), tanh_fast(e0.y * d0.y));
            uint32_t p1 = pack_bf16x2(tanh_fast(e0.z * d0.z), tanh_fast(e0.w * d0.w));
            uint32_t p2 = pack_bf16x2(tanh_fast(e1.x * d1.x), tanh_fast(e1.y * d1.y));
            uint32_t p3 = pack_bf16x2(tanh_fast(e1.z * d1.z), tanh_fast(e1.w * d1.w));
            uint32_t c = (uint32_t)(k >> 3);
            uint32_t addr = mrow + ((c ^ msw) << 4);
            asm volatile("st.shared.v4.b32 [%0], {%1,%2,%3,%4};"
                         :: "r"(addr), "r"(p0), "r"(p1), "r"(p2), "r"(p3) : "memory");
        }
    }
    __syncthreads();

    // ---- prologue: prefetch B tiles 0,1 ----
    load_b_tile(0, b_base, tid);
    load_b_tile(1, b_base, tid);

    // ---- per-lane ldmatrix addressing ----
    const int rowA = warp_m * 32 + (lane & 15);
    const uint32_t a_lane = a_base + (uint32_t)rowA * 1024u;
    const uint32_t swzA = (uint32_t)(rowA & 7);
    const uint32_t cbaseA = (uint32_t)(lane >> 4);
    const int n_row_base = warp_n * 64 + ((lane >> 4) << 3) + (lane & 7);
    const uint32_t kh = (uint32_t)((lane >> 3) & 1);
    const uint32_t swzB = (uint32_t)(lane & 7);
    uint32_t rowoffB[4];
#pragma unroll
    for (int p = 0; p < 4; p++) rowoffB[p] = (uint32_t)(n_row_base + p * 16) * 128u;

    // ---- per-row epilogue state ----
    float sm[4], blankv[4], tgtv[4];
    int tg[4];
#pragma unroll
    for (int g = 0; g < 4; g++) {
        sm[g] = 0.f; blankv[g] = 0.f; tgtv[g] = 0.f;
        int m = warp_m * 32 + (g >> 1) * 16 + (g & 1) * 8 + (lane >> 2);
        tg[g] = tgtm[m];
    }

    float acc[2][8][4];

#pragma unroll 1
    for (int bt = 0; bt < NTILES; bt++) {
        const int ktl = bt & 7;
        if (bt < NTILES - 1) asm volatile("cp.async.wait_group 1;" ::: "memory");
        else                 asm volatile("cp.async.wait_group 0;" ::: "memory");
        __syncthreads();
        if (bt + 2 < NTILES) load_b_tile(bt + 2, b_base, tid);

        if (ktl == 0) {
#pragma unroll
            for (int mi = 0; mi < 2; mi++)
#pragma unroll
                for (int nf = 0; nf < 8; nf++)
#pragma unroll
                    for (int j = 0; j < 4; j++) acc[mi][nf][j] = 0.f;
        }

        const uint32_t bbuf = b_base + (uint32_t)(bt % NBUF) * BT_BYTES;
#pragma unroll
        for (int s = 0; s < 4; s++) {
            uint32_t a0[4], a1[4];
            uint32_t cA = (uint32_t)(ktl * 8 + s * 2) + cbaseA;
            uint32_t aaddr = a_lane + ((cA ^ swzA) << 4);
            ldsm_x4(a0, aaddr);
            ldsm_x4(a1, aaddr + 16384u);
            uint32_t b[4][4];
            uint32_t cB = ((uint32_t)(s * 2) + kh) ^ swzB;
#pragma unroll
            for (int p = 0; p < 4; p++)
                ldsm_x4(b[p], bbuf + rowoffB[p] + (cB << 4));
#pragma unroll
            for (int p = 0; p < 4; p++) {
                mma_bf16(acc[0][2 * p],     a0, b[p][0], b[p][1]);
                mma_bf16(acc[0][2 * p + 1], a0, b[p][2], b[p][3]);
                mma_bf16(acc[1][2 * p],     a1, b[p][0], b[p][1]);
                mma_bf16(acc[1][2 * p + 1], a1, b[p][2], b[p][3]);
            }
        }

        if (ktl == 7) {
            const int nc = bt >> 3;
            const int vbase = nc * 256 + warp_n * 64 + (lane & 3) * 2;
#pragma unroll
            for (int g = 0; g < 4; g++) {
                const int mi = g >> 1, hf = (g & 1) * 2;
                float ls = 0.f;
#pragma unroll
                for (int nf = 0; nf < 8; nf++)
                    ls += __expf(acc[mi][nf][hf]) + __expf(acc[mi][nf][hf + 1]);
                ls += __shfl_xor_sync(FM, ls, 1);
                ls += __shfl_xor_sync(FM, ls, 2);
                sm[g] += ls;
#pragma unroll
                for (int nf = 0; nf < 8; nf++) {
                    int v0 = vbase + nf * 8;
                    if (v0 == 0)         blankv[g] = acc[mi][nf][hf];
                    if (v0 == tg[g])     tgtv[g]   = acc[mi][nf][hf];
                    if (v0 + 1 == tg[g]) tgtv[g]   = acc[mi][nf][hf + 1];
                }
            }
        }
    }

    // gather captured values across the 4 lanes of each row group
#pragma unroll
    for (int g = 0; g < 4; g++) {
        tgtv[g]   += __shfl_xor_sync(FM, tgtv[g], 1);
        tgtv[g]   += __shfl_xor_sync(FM, tgtv[g], 2);
        blankv[g] += __shfl_xor_sync(FM, blankv[g], 1);
        blankv[g] += __shfl_xor_sync(FM, blankv[g], 2);
    }

    // reuse B buffer smem for the cross-n-warp combine
    __syncthreads();
    float* ssum   = reinterpret_cast<float*>(dyn) + ((b_base - smem_u32(dyn)) >> 2);
    float* stgtv  = ssum + 4 * MTILE;
    float* sblank = stgtv + 4 * MTILE;

    if ((lane & 3) == 0) {
#pragma unroll
        for (int g = 0; g < 4; g++) {
            int m = warp_m * 32 + (g >> 1) * 16 + (g & 1) * 8 + (lane >> 2);
            ssum[warp_n * MTILE + m]  = sm[g];
            stgtv[warp_n * MTILE + m] = tgtv[g];
            if (warp_n == 0) sblank[m] = blankv[g];
        }
    }
    __syncthreads();

    if (tid < MTILE) {
        int m = tid;
        float lse = __logf(ssum[m] + ssum[MTILE + m] + ssum[2 * MTILE + m] + ssum[3 * MTILE + m]);
        int g = g0 + m;
        int b = g / (TT * UP);
        int r = g - b * (TT * UP);
        int t = r / UP, u = r - t * UP;
        g_blank[g] = sblank[m] - lse;
        if (u < UU) {
            int h = (tgtm[m] >> 6) & 3;   // which 64-col N-warp owns target
            g_emit[(size_t)(b * TT + t) * UU + u] = stgtv[h * MTILE + m] - lse;
        }
    }
}

// =====================================================================
// K4: alpha DP — branchless anti-diagonal wavefront.
// Guard-padded smem staging makes ALL loads in-bounds with pure
// incremental addressing; NEG-annihilation makes masks unnecessary
// (invalid cells stay ~-1e30 and never feed valid cells).
// =====================================================================
__device__ __forceinline__ float lse2(float a, float b) {
    float m = fmaxf(a, b);
    float n = fminf(a, b);
    return m + __logf(1.f + __expf(n - m));
}

#define DP_PAD0 4096                     // covers min index -4096 (d=1, u=64)
#define DP_BL_FLOATS (TT*UP)             // 16640
#define DP_EM_FLOATS (TT*UU)             // 16384
#define DP_PAD1 4224                     // covers max em prefetch overshoot
#define DP_TOT (DP_PAD0 + DP_BL_FLOATS + DP_EM_FLOATS + DP_PAD1)   // 41344
#define DP_SMEM_BYTES (DP_TOT * 4)       // 165376

__global__ void __launch_bounds__(256, 1) dp_kernel(
    const int* __restrict__ in_len, const int* __restrict__ tgt_len)
{
    extern __shared__ float sdp[];
    float* sbl = sdp + DP_PAD0;            // [TT*UP]
    float* sem = sbl + DP_BL_FLOATS;       // [TT*UU]

    const int b = blockIdx.x;
    const int tid = threadIdx.x;

    // ---- zero guard pads (deterministic annihilated-arm reads) ----
    {
        float4 z = make_float4(0.f, 0.f, 0.f, 0.f);
        float4* gp0 = reinterpret_cast<float4*>(sdp);
        for (int q = tid; q < DP_PAD0 / 4; q += 256) gp0[q] = z;
        float4* gp1 = reinterpret_cast<float4*>(sem + DP_EM_FLOATS);
        for (int q = tid; q < DP_PAD1 / 4; q += 256) gp1[q] = z;
    }
    // ---- stage blank/emit into smem (float4, coalesced) ----
    {
        const float4* gb = reinterpret_cast<const float4*>(g_blank + (size_t)b * DP_BL_FLOATS);
        float4* sb = reinterpret_cast<float4*>(sbl);
#pragma unroll
        for (int i = 0; i < DP_BL_FLOATS / 4 / 256 + 1; i++) {
            int q = tid + i * 256;
            if (q < DP_BL_FLOATS / 4) sb[q] = gb[q];
        }
        const float4* ge = reinterpret_cast<const float4*>(g_emit + (size_t)b * DP_EM_FLOATS);
        float4* se = reinterpret_cast<float4*>(sem);
#pragma unroll
        for (int i = 0; i < DP_EM_FLOATS / 4 / 256; i++) {
            int q = tid + i * 256;
            se[q] = ge[q];
        }
    }
    __syncthreads();

    if (tid >= 32) return;
    const int lane = tid;
    const int til = in_len[b];
    const int ul  = tgt_len[b];
    const int dmax = til - 1 + ul;
    const float NEG = -1e30f;
    const unsigned FM = 0xffffffffu;

    int u[3], uc[3];
    float al[3];
#pragma unroll
    for (int j = 0; j < 3; j++) {
        u[j] = lane * 3 + j;
        uc[j] = (u[j] > UU) ? UU : u[j];     // clamped for addressing only
        al[j] = (u[j] == 0) ? 0.f : NEG;
    }

    // incremental indices for diagonal d: ibl = (d-1-uc)*UP + uc, iem = (d-uc)*UU + uc-1
    int ibl[3], iem[3];
#pragma unroll
    for (int j = 0; j < 3; j++) {
        ibl[j] = -UU * uc[j];                // d=1: (1-1-uc)*65 + uc = -64*uc
        iem[j] = (UU - 1) - (UU - 1) * uc[j];// d=1: (1-uc)*64 + uc-1 = 63 - 63*uc
    }

    float bl[3], em[3];
#pragma unroll
    for (int j = 0; j < 3; j++) { bl[j] = sbl[ibl[j]]; em[j] = sem[iem[j]]; }

#pragma unroll 1
    for (int d = 1; d <= dmax; d++) {
        // prefetch operands for d+1 (pure increment; guards make it in-bounds)
        float nbl[3], nem[3];
#pragma unroll
        for (int j = 0; j < 3; j++) {
            ibl[j] += UP; iem[j] += UU;
            nbl[j] = sbl[ibl[j]];
            nem[j] = sem[iem[j]];
        }

        float nb0 = __shfl_up_sync(FM, al[2], 1);
        if (lane == 0) nb0 = NEG;

        float nw0 = lse2(al[0] + bl[0], nb0   + em[0]);
        float nw1 = lse2(al[1] + bl[1], al[0] + em[1]);
        float nw2 = lse2(al[2] + bl[2], al[1] + em[2]);
        al[0] = nw0; al[1] = nw1; al[2] = nw2;

        bl[0] = nbl[0]; bl[1] = nbl[1]; bl[2] = nbl[2];
        em[0] = nem[0]; em[1] = nem[1]; em[2] = nem[2];
    }

    // after step dmax, al[j] at u==ul holds alpha(til-1, ul)
#pragma unroll
    for (int j = 0; j < 3; j++) {
        if (u[j] == ul)
            g_final[b] = al[j] + sbl[(til - 1) * UP + ul];
    }
}

__global__ void finalize_kernel(float* out) {
    out[0] = -0.25f * (g_final[0] + g_final[1] + g_final[2] + g_final[3]);
}

// =====================================================================
// launch
// =====================================================================
extern "C" void kernel_launch(void* const* d_in, const int* in_sizes, int n_in,
                              void* d_out, int out_size)
{
    const float* enc     = (const float*)d_in[0];
    const float* dec     = (const float*)d_in[1];
    const int*   targets = (const int*)  d_in[2];
    const int*   in_len  = (const int*)  d_in[3];
    const int*   tgt_len = (const int*)  d_in[4];
    const float* W_enc   = (const float*)d_in[5];
    const float* b_enc   = (const float*)d_in[6];
    const float* W_dec   = (const float*)d_in[7];
    const float* b_dec   = (const float*)d_in[8];
    const float* W_proj  = (const float*)d_in[9];

    void *pe = nullptr, *pd = nullptr;
    cudaGetSymbolAddress(&pe, g_enc_h);
    cudaGetSymbolAddress(&pd, g_dec_h);

    const int smem_joint = 1024 + A_BYTES + NBUF * BT_BYTES;   // 230400 B
    cudaFuncSetAttribute(joint_kernel, cudaFuncAttributeMaxDynamicSharedMemorySize, smem_joint);
    cudaFuncSetAttribute(dp_kernel, cudaFuncAttributeMaxDynamicSharedMemorySize, DP_SMEM_BYTES);

    convert_wp_kernel<<<(VV * DJ) / 256, 256>>>(W_proj);

    dim3 gg((BB * TT + 63) / 64, DJ / 64, 2);
    gemm_bias_kernel<<<gg, 256>>>(enc, W_enc, b_enc, (float*)pe, BB * TT,
                                  dec, W_dec, b_dec, (float*)pd, BB * UP);

    joint_kernel<<<(BB * TT * UP) / MTILE, JTHREADS, smem_joint>>>(targets, in_len);

    dp_kernel<<<BB, 256, DP_SMEM_BYTES>>>(in_len, tgt_len);

    finalize_kernel<<<1, 1>>>((float*)d_out);
}

// round 16
// speedup vs baseline: 1.5244x; 1.1010x over previous
#include <cuda_runtime.h>
#include <cuda_bf16.h>
#include <math.h>
#include <stdint.h>

#define BB 4
#define TT 256
#define UU 64
#define UP 65          // U+1
#define DJ 512
#define VV 1024
#define MTILE 128      // lattice rows per joint CTA
#define A_BYTES (MTILE*DJ*2)     // 131072
#define BT_BYTES (256*128)       // 32768: 256n x 64k bf16, 128B rows (SW128 atom)
#define NBUF 3
#define NTILES 32                // 4 nc x 8 ktile
#define JTHREADS 512

// ---------------- scratch ----------------
__device__ float g_enc_h[BB*TT*DJ];
__device__ float g_dec_h[BB*UP*DJ];
__device__ float g_blank[BB*TT*UP];
__device__ float g_emit [BB*TT*UU];
__device__ __nv_bfloat16 g_wp[VV*DJ];   // W_proj bf16 [V][K] row-major

// ---------------- helpers ----------------
__device__ __forceinline__ uint32_t smem_u32(const void* p) {
    uint32_t a;
    asm("{ .reg .u64 t; cvta.to.shared.u64 t, %1; cvt.u32.u64 %0, t; }" : "=r"(a) : "l"(p));
    return a;
}
__device__ __forceinline__ float tanh_fast(float x) {
    float r; asm("tanh.approx.f32 %0, %1;" : "=f"(r) : "f"(x)); return r;
}
__device__ __forceinline__ uint32_t pack_bf16x2(float lo, float hi) {
    uint32_t r; asm("cvt.rn.bf16x2.f32 %0, %1, %2;" : "=r"(r) : "f"(hi), "f"(lo)); return r;
}
__device__ __forceinline__ void cp_async16(uint32_t dst, const void* src) {
    asm volatile("cp.async.cg.shared.global [%0], [%1], 16;\n" :: "r"(dst), "l"(src) : "memory");
}
__device__ __forceinline__ void ldsm_x4(uint32_t (&r)[4], uint32_t addr) {
    asm volatile("ldmatrix.sync.aligned.m8n8.x4.shared.b16 {%0,%1,%2,%3}, [%4];"
                 : "=r"(r[0]), "=r"(r[1]), "=r"(r[2]), "=r"(r[3]) : "r"(addr));
}
__device__ __forceinline__ void mma_bf16(float (&c)[4], const uint32_t (&a)[4],
                                         uint32_t b0, uint32_t b1) {
    asm volatile(
        "mma.sync.aligned.m16n8k16.row.col.f32.bf16.bf16.f32 "
        "{%0,%1,%2,%3}, {%4,%5,%6,%7}, {%8,%9}, {%0,%1,%2,%3};"
        : "+f"(c[0]), "+f"(c[1]), "+f"(c[2]), "+f"(c[3])
        : "r"(a[0]), "r"(a[1]), "r"(a[2]), "r"(a[3]), "r"(b0), "r"(b1));
}

// =====================================================================
// K1: prep — fused W_proj convert + enc/dec projections (one launch)
// blocks [0,128): enc gemm tiles 16m x 8n (64x64)
// blocks [128,168): dec gemm tiles 5m x 8n
// blocks [168,2216): W_proj fp32->bf16 convert
// =====================================================================
#define PREP_GEMM_BLOCKS 168
#define PREP_BLOCKS (PREP_GEMM_BLOCKS + (VV*DJ)/256)

__global__ void __launch_bounds__(128) prep_kernel(
    const float* __restrict__ enc, const float* __restrict__ Wenc,
    const float* __restrict__ benc,
    const float* __restrict__ dec, const float* __restrict__ Wdec,
    const float* __restrict__ bdec,
    const float* __restrict__ Wp, const int* __restrict__ in_len)
{
    const int bid = blockIdx.x;
    const int tid = threadIdx.x;

    if (bid >= PREP_GEMM_BLOCKS) {
        int idx = (bid - PREP_GEMM_BLOCKS) * 256 + tid * 2;
        float2 v = *reinterpret_cast<const float2*>(&Wp[idx]);
        *reinterpret_cast<uint32_t*>(&g_wp[idx]) = pack_bf16x2(v.x, v.y);
        return;
    }

    const float* A; const float* W; const float* bias; float* C; int M;
    int mt, nt;
    if (bid < 128) {
        A = enc; W = Wenc; bias = benc; M = BB * TT;
        void* p; asm("" ::: "memory");
        C = g_enc_h;
        mt = bid >> 3; nt = bid & 7;
        // dead-row skip: rows m0..m0+63 all share batch b; skip if t_min >= til
        int m0 = mt * 64;
        int b = m0 >> 8, t_min = m0 & 255;
        if (t_min >= in_len[b]) return;
    } else {
        A = dec; W = Wdec; bias = bdec; M = BB * UP;
        C = g_dec_h;
        int lb = bid - 128;
        mt = lb >> 3; nt = lb & 7;
    }
    const int m0 = mt * 64;
    const int n0 = nt * 64;
    const int K = 512;

    __shared__ float As[16][72];
    __shared__ float Ws[16][72];
    const int ty = tid >> 4;        // 0..7  -> 8 rows each
    const int tx = tid & 15;        // 0..15 -> 4 cols each
    const int lrow = tid >> 1;      // 0..63
    const int lk   = (tid & 1) * 8; // 0 or 8

    float acc[8][4];
#pragma unroll
    for (int i = 0; i < 8; i++)
#pragma unroll
        for (int j = 0; j < 4; j++) acc[i][j] = 0.f;

    for (int k0 = 0; k0 < K; k0 += 16) {
        const int gm = m0 + lrow;
        float4 a0, a1;
        if (gm < M) {
            a0 = *reinterpret_cast<const float4*>(&A[(size_t)gm * K + k0 + lk]);
            a1 = *reinterpret_cast<const float4*>(&A[(size_t)gm * K + k0 + lk + 4]);
        } else {
            a0 = make_float4(0.f, 0.f, 0.f, 0.f); a1 = a0;
        }
        const int gn = n0 + lrow;   // N=512, always valid
        float4 w0 = *reinterpret_cast<const float4*>(&W[(size_t)gn * K + k0 + lk]);
        float4 w1 = *reinterpret_cast<const float4*>(&W[(size_t)gn * K + k0 + lk + 4]);
        __syncthreads();
        As[lk + 0][lrow] = a0.x; As[lk + 1][lrow] = a0.y;
        As[lk + 2][lrow] = a0.z; As[lk + 3][lrow] = a0.w;
        As[lk + 4][lrow] = a1.x; As[lk + 5][lrow] = a1.y;
        As[lk + 6][lrow] = a1.z; As[lk + 7][lrow] = a1.w;
        Ws[lk + 0][lrow] = w0.x; Ws[lk + 1][lrow] = w0.y;
        Ws[lk + 2][lrow] = w0.z; Ws[lk + 3][lrow] = w0.w;
        Ws[lk + 4][lrow] = w1.x; Ws[lk + 5][lrow] = w1.y;
        Ws[lk + 6][lrow] = w1.z; Ws[lk + 7][lrow] = w1.w;
        __syncthreads();
#pragma unroll
        for (int kk = 0; kk < 16; kk++) {
            float4 av0 = *reinterpret_cast<const float4*>(&As[kk][ty * 8]);
            float4 av1 = *reinterpret_cast<const float4*>(&As[kk][ty * 8 + 4]);
            float4 wv  = *reinterpret_cast<const float4*>(&Ws[kk][tx * 4]);
            float a[8] = {av0.x, av0.y, av0.z, av0.w, av1.x, av1.y, av1.z, av1.w};
            float w[4] = {wv.x, wv.y, wv.z, wv.w};
#pragma unroll
            for (int i = 0; i < 8; i++)
#pragma unroll
                for (int j = 0; j < 4; j++)
                    acc[i][j] = fmaf(a[i], w[j], acc[i][j]);
        }
    }

    float4 bv = *reinterpret_cast<const float4*>(&bias[n0 + tx * 4]);
#pragma unroll
    for (int i = 0; i < 8; i++) {
        int gm = m0 + ty * 8 + i;
        if (gm < M) {
            float4 o;
            o.x = acc[i][0] + bv.x; o.y = acc[i][1] + bv.y;
            o.z = acc[i][2] + bv.z; o.w = acc[i][3] + bv.w;
            *reinterpret_cast<float4*>(&C[(size_t)gm * DJ + n0 + tx * 4]) = o;
        }
    }
}

// =====================================================================
// K3: mma.sync bf16 joint GEMM + fused log-softmax + dead-tile skip
// =====================================================================
__device__ __forceinline__ void load_b_tile(int bt, uint32_t b_base, int tid) {
    uint32_t buf = b_base + (uint32_t)(bt % NBUF) * BT_BYTES;
    const int nc = bt >> 3, ktl = bt & 7;
    const int n = tid >> 1;                 // 256 rows, 2 threads/row
    const int c0 = (tid & 1) * 4;           // 4 x 16B per thread
    const __nv_bfloat16* src = g_wp + ((size_t)(nc * 256 + n) * DJ + ktl * 64 + c0 * 8);
    const uint32_t row = buf + (uint32_t)n * 128u;
    const uint32_t sw = (uint32_t)(n & 7);
#pragma unroll
    for (int j = 0; j < 4; j++) {
        uint32_t c = (uint32_t)(c0 + j);
        cp_async16(row + ((c ^ sw) << 4), src + j * 8);
    }
    asm volatile("cp.async.commit_group;" ::: "memory");
}

__global__ void __launch_bounds__(JTHREADS, 1) joint_kernel(
    const int* __restrict__ targets, const int* __restrict__ in_len)
{
    extern __shared__ __align__(16) char dyn[];
    __shared__ int tgtm[MTILE];

    const int g0 = blockIdx.x * MTILE;
    {   // dead-tile early exit (uniform across CTA, before any barrier)
        int b = g0 / (TT * UP);
        int t_min = (g0 - b * (TT * UP)) / UP;
        if (t_min >= in_len[b]) return;
    }

    const uint32_t base = (smem_u32(dyn) + 1023u) & ~1023u;
    const uint32_t a_base = base;
    const uint32_t b_base = base + A_BYTES;

    const int tid  = threadIdx.x;
    const int lane = tid & 31;
    const int wid  = tid >> 5;
    const int warp_m = wid & 3;     // 4 M-warps of 32 rows
    const int warp_n = wid >> 2;    // 4 N-warps of 64 cols (over 256-col chunk)
    const unsigned FM = 0xffffffffu;

    if (tid < MTILE) {
        int g = g0 + tid;
        int b = g / (TT * UP);
        int r = g - b * (TT * UP);
        int u = r % UP;
        tgtm[tid] = (u < UU) ? targets[b * UU + u] : -1;
    }

    // ---- generate h tile into XOR-swizzled A (bf16); each thread 128 k ----
    {
        const int m = tid >> 2;
        const int kq = (tid & 3) * 128;
        int g = g0 + m;
        int b = g / (TT * UP);
        int r = g - b * (TT * UP);
        int t = r / UP, u = r - t * UP;
        const float4* er = reinterpret_cast<const float4*>(
            g_enc_h + ((size_t)(b * TT + t)) * DJ + kq);
        const float4* dr = reinterpret_cast<const float4*>(
            g_dec_h + ((size_t)(b * UP + u)) * DJ + kq);
        const uint32_t mrow = a_base + (uint32_t)m * 1024u;
        const uint32_t msw = (uint32_t)(m & 7);
#pragma unroll 4
        for (int i = 0; i < 16; i++) {
            int k = kq + i * 8;
            float4 e0 = er[i * 2], e1 = er[i * 2 + 1];
            float4 d0 = dr[i * 2], d1 = dr[i * 2 + 1];
            uint32_t p0 = pack_bf16x2(tanh_fast(e0.x * d0.x), tanh_fast(e0.y * d0.y));
            uint32_t p1 = pack_bf16x2(tanh_fast(e0.z * d0.z), tanh_fast(e0.w * d0.w));
            uint32_t p2 = pack_bf16x2(tanh_fast(e1.x * d1.x), tanh_fast(e1.y * d1.y));
            uint32_t p3 = pack_bf16x2(tanh_fast(e1.z * d1.z), tanh_fast(e1.w * d1.w));
            uint32_t c = (uint32_t)(k >> 3);
            uint32_t addr = mrow + ((c ^ msw) << 4);
            asm volatile("st.shared.v4.b32 [%0], {%1,%2,%3,%4};"
                         :: "r"(addr), "r"(p0), "r"(p1), "r"(p2), "r"(p3) : "memory");
        }
    }
    __syncthreads();

    // ---- prologue: prefetch B tiles 0,1 ----
    load_b_tile(0, b_base, tid);
    load_b_tile(1, b_base, tid);

    // ---- per-lane ldmatrix addressing ----
    const int rowA = warp_m * 32 + (lane & 15);
    const uint32_t a_lane = a_base + (uint32_t)rowA * 1024u;
    const uint32_t swzA = (uint32_t)(rowA & 7);
    const uint32_t cbaseA = (uint32_t)(lane >> 4);
    const int n_row_base = warp_n * 64 + ((lane >> 4) << 3) + (lane & 7);
    const uint32_t kh = (uint32_t)((lane >> 3) & 1);
    const uint32_t swzB = (uint32_t)(lane & 7);
    uint32_t rowoffB[4];
#pragma unroll
    for (int p = 0; p < 4; p++) rowoffB[p] = (uint32_t)(n_row_base + p * 16) * 128u;

    // ---- per-row epilogue state ----
    float sm[4], blankv[4], tgtv[4];
    int tg[4];
#pragma unroll
    for (int g = 0; g < 4; g++) {
        sm[g] = 0.f; blankv[g] = 0.f; tgtv[g] = 0.f;
        int m = warp_m * 32 + (g >> 1) * 16 + (g & 1) * 8 + (lane >> 2);
        tg[g] = tgtm[m];
    }

    float acc[2][8][4];

#pragma unroll 1
    for (int bt = 0; bt < NTILES; bt++) {
        const int ktl = bt & 7;
        if (bt < NTILES - 1) asm volatile("cp.async.wait_group 1;" ::: "memory");
        else                 asm volatile("cp.async.wait_group 0;" ::: "memory");
        __syncthreads();
        if (bt + 2 < NTILES) load_b_tile(bt + 2, b_base, tid);

        if (ktl == 0) {
#pragma unroll
            for (int mi = 0; mi < 2; mi++)
#pragma unroll
                for (int nf = 0; nf < 8; nf++)
#pragma unroll
                    for (int j = 0; j < 4; j++) acc[mi][nf][j] = 0.f;
        }

        const uint32_t bbuf = b_base + (uint32_t)(bt % NBUF) * BT_BYTES;
#pragma unroll
        for (int s = 0; s < 4; s++) {
            uint32_t a0[4], a1[4];
            uint32_t cA = (uint32_t)(ktl * 8 + s * 2) + cbaseA;
            uint32_t aaddr = a_lane + ((cA ^ swzA) << 4);
            ldsm_x4(a0, aaddr);
            ldsm_x4(a1, aaddr + 16384u);
            uint32_t b[4][4];
            uint32_t cB = ((uint32_t)(s * 2) + kh) ^ swzB;
#pragma unroll
            for (int p = 0; p < 4; p++)
                ldsm_x4(b[p], bbuf + rowoffB[p] + (cB << 4));
#pragma unroll
            for (int p = 0; p < 4; p++) {
                mma_bf16(acc[0][2 * p],     a0, b[p][0], b[p][1]);
                mma_bf16(acc[0][2 * p + 1], a0, b[p][2], b[p][3]);
                mma_bf16(acc[1][2 * p],     a1, b[p][0], b[p][1]);
                mma_bf16(acc[1][2 * p + 1], a1, b[p][2], b[p][3]);
            }
        }

        if (ktl == 7) {
            const int nc = bt >> 3;
            const int vbase = nc * 256 + warp_n * 64 + (lane & 3) * 2;
#pragma unroll
            for (int g = 0; g < 4; g++) {
                const int mi = g >> 1, hf = (g & 1) * 2;
                float ls = 0.f;
#pragma unroll
                for (int nf = 0; nf < 8; nf++)
                    ls += __expf(acc[mi][nf][hf]) + __expf(acc[mi][nf][hf + 1]);
                ls += __shfl_xor_sync(FM, ls, 1);
                ls += __shfl_xor_sync(FM, ls, 2);
                sm[g] += ls;
#pragma unroll
                for (int nf = 0; nf < 8; nf++) {
                    int v0 = vbase + nf * 8;
                    if (v0 == 0)         blankv[g] = acc[mi][nf][hf];
                    if (v0 == tg[g])     tgtv[g]   = acc[mi][nf][hf];
                    if (v0 + 1 == tg[g]) tgtv[g]   = acc[mi][nf][hf + 1];
                }
            }
        }
    }

    // gather captured values across the 4 lanes of each row group
#pragma unroll
    for (int g = 0; g < 4; g++) {
        tgtv[g]   += __shfl_xor_sync(FM, tgtv[g], 1);
        tgtv[g]   += __shfl_xor_sync(FM, tgtv[g], 2);
        blankv[g] += __shfl_xor_sync(FM, blankv[g], 1);
        blankv[g] += __shfl_xor_sync(FM, blankv[g], 2);
    }

    // reuse B buffer smem for the cross-n-warp combine
    __syncthreads();
    float* ssum   = reinterpret_cast<float*>(dyn) + ((b_base - smem_u32(dyn)) >> 2);
    float* stgtv  = ssum + 4 * MTILE;
    float* sblank = stgtv + 4 * MTILE;

    if ((lane & 3) == 0) {
#pragma unroll
        for (int g = 0; g < 4; g++) {
            int m = warp_m * 32 + (g >> 1) * 16 + (g & 1) * 8 + (lane >> 2);
            ssum[warp_n * MTILE + m]  = sm[g];
            stgtv[warp_n * MTILE + m] = tgtv[g];
            if (warp_n == 0) sblank[m] = blankv[g];
        }
    }
    __syncthreads();

    if (tid < MTILE) {
        int m = tid;
        float lse = __logf(ssum[m] + ssum[MTILE + m] + ssum[2 * MTILE + m] + ssum[3 * MTILE + m]);
        int g = g0 + m;
        int b = g / (TT * UP);
        int r = g - b * (TT * UP);
        int t = r / UP, u = r - t * UP;
        g_blank[g] = sblank[m] - lse;
        if (u < UU) {
            int h = (tgtm[m] >> 6) & 3;   // which 64-col N-warp owns target
            g_emit[(size_t)(b * TT + t) * UU + u] = stgtv[h * MTILE + m] - lse;
        }
    }
}

// =====================================================================
// K4: alpha DP — branchless anti-diagonal wavefront (R15) + fused
// finalize: atomicAdd(-0.25*final) into d_out (zeroed by memsetAsync).
// =====================================================================
__device__ __forceinline__ float lse2(float a, float b) {
    float m = fmaxf(a, b);
    float n = fminf(a, b);
    return m + __logf(1.f + __expf(n - m));
}

#define DP_PAD0 4096
#define DP_BL_FLOATS (TT*UP)             // 16640
#define DP_EM_FLOATS (TT*UU)             // 16384
#define DP_PAD1 4224
#define DP_TOT (DP_PAD0 + DP_BL_FLOATS + DP_EM_FLOATS + DP_PAD1)
#define DP_SMEM_BYTES (DP_TOT * 4)       // 165376

__global__ void __launch_bounds__(256, 1) dp_kernel(
    const int* __restrict__ in_len, const int* __restrict__ tgt_len,
    float* __restrict__ out)
{
    extern __shared__ float sdp[];
    float* sbl = sdp + DP_PAD0;
    float* sem = sbl + DP_BL_FLOATS;

    const int b = blockIdx.x;
    const int tid = threadIdx.x;

    {
        float4 z = make_float4(0.f, 0.f, 0.f, 0.f);
        float4* gp0 = reinterpret_cast<float4*>(sdp);
        for (int q = tid; q < DP_PAD0 / 4; q += 256) gp0[q] = z;
        float4* gp1 = reinterpret_cast<float4*>(sem + DP_EM_FLOATS);
        for (int q = tid; q < DP_PAD1 / 4; q += 256) gp1[q] = z;
    }
    {
        const float4* gb = reinterpret_cast<const float4*>(g_blank + (size_t)b * DP_BL_FLOATS);
        float4* sb = reinterpret_cast<float4*>(sbl);
#pragma unroll
        for (int i = 0; i < DP_BL_FLOATS / 4 / 256 + 1; i++) {
            int q = tid + i * 256;
            if (q < DP_BL_FLOATS / 4) sb[q] = gb[q];
        }
        const float4* ge = reinterpret_cast<const float4*>(g_emit + (size_t)b * DP_EM_FLOATS);
        float4* se = reinterpret_cast<float4*>(sem);
#pragma unroll
        for (int i = 0; i < DP_EM_FLOATS / 4 / 256; i++) {
            int q = tid + i * 256;
            se[q] = ge[q];
        }
    }
    __syncthreads();

    if (tid >= 32) return;
    const int lane = tid;
    const int til = in_len[b];
    const int ul  = tgt_len[b];
    const int dmax = til - 1 + ul;
    const float NEG = -1e30f;
    const unsigned FM = 0xffffffffu;

    int u[3], uc[3];
    float al[3];
#pragma unroll
    for (int j = 0; j < 3; j++) {
        u[j] = lane * 3 + j;
        uc[j] = (u[j] > UU) ? UU : u[j];
        al[j] = (u[j] == 0) ? 0.f : NEG;
    }

    int ibl[3], iem[3];
#pragma unroll
    for (int j = 0; j < 3; j++) {
        ibl[j] = -UU * uc[j];
        iem[j] = (UU - 1) - (UU - 1) * uc[j];
    }

    float bl[3], em[3];
#pragma unroll
    for (int j = 0; j < 3; j++) { bl[j] = sbl[ibl[j]]; em[j] = sem[iem[j]]; }

#pragma unroll 1
    for (int d = 1; d <= dmax; d++) {
        float nbl[3], nem[3];
#pragma unroll
        for (int j = 0; j < 3; j++) {
            ibl[j] += UP; iem[j] += UU;
            nbl[j] = sbl[ibl[j]];
            nem[j] = sem[iem[j]];
        }

        float nb0 = __shfl_up_sync(FM, al[2], 1);
        if (lane == 0) nb0 = NEG;

        float nw0 = lse2(al[0] + bl[0], nb0   + em[0]);
        float nw1 = lse2(al[1] + bl[1], al[0] + em[1]);
        float nw2 = lse2(al[2] + bl[2], al[1] + em[2]);
        al[0] = nw0; al[1] = nw1; al[2] = nw2;

        bl[0] = nbl[0]; bl[1] = nbl[1]; bl[2] = nbl[2];
        em[0] = nem[0]; em[1] = nem[1]; em[2] = nem[2];
    }

#pragma unroll
    for (int j = 0; j < 3; j++) {
        if (u[j] == ul)
            atomicAdd(out, -0.25f * (al[j] + sbl[(til - 1) * UP + ul]));
    }
}

// =====================================================================
// launch
// =====================================================================
extern "C" void kernel_launch(void* const* d_in, const int* in_sizes, int n_in,
                              void* d_out, int out_size)
{
    const float* enc     = (const float*)d_in[0];
    const float* dec     = (const float*)d_in[1];
    const int*   targets = (const int*)  d_in[2];
    const int*   in_len  = (const int*)  d_in[3];
    const int*   tgt_len = (const int*)  d_in[4];
    const float* W_enc   = (const float*)d_in[5];
    const float* b_enc   = (const float*)d_in[6];
    const float* W_dec   = (const float*)d_in[7];
    const float* b_dec   = (const float*)d_in[8];
    const float* W_proj  = (const float*)d_in[9];

    const int smem_joint = 1024 + A_BYTES + NBUF * BT_BYTES;   // 230400 B
    cudaFuncSetAttribute(joint_kernel, cudaFuncAttributeMaxDynamicSharedMemorySize, smem_joint);
    cudaFuncSetAttribute(dp_kernel, cudaFuncAttributeMaxDynamicSharedMemorySize, DP_SMEM_BYTES);

    cudaMemsetAsync(d_out, 0, sizeof(float));

    prep_kernel<<<PREP_BLOCKS, 128>>>(enc, W_enc, b_enc,
                                      dec, W_dec, b_dec,
                                      W_proj, in_len);

    joint_kernel<<<(BB * TT * UP) / MTILE, JTHREADS, smem_joint>>>(targets, in_len);

    dp_kernel<<<BB, 256, DP_SMEM_BYTES>>>(in_len, tgt_len, (float*)d_out);
}

// round 17
// speedup vs baseline: 1.5632x; 1.0254x over previous
#include <cuda_runtime.h>
#include <cuda_bf16.h>
#include <math.h>
#include <stdint.h>

#define BB 4
#define TT 256
#define UU 64
#define UP 65          // U+1
#define DJ 512
#define VV 1024
#define MTILE 128      // lattice rows per joint CTA
#define A_BYTES (MTILE*DJ*2)     // 131072
#define BT_BYTES (256*128)       // 32768: 256n x 64k bf16, 128B rows (SW128 atom)
#define NBUF 3
#define NTILES 32                // 4 nc x 8 ktile
#define JTHREADS 512

// ---------------- scratch ----------------
__device__ float g_enc_h[BB*TT*DJ];
__device__ float g_dec_h[BB*UP*DJ];
__device__ float g_blank[BB*TT*UP];
__device__ float g_emit [BB*TT*UU];
__device__ __nv_bfloat16 g_wp[VV*DJ];   // W_proj bf16 [V][K] row-major

// ---------------- helpers ----------------
__device__ __forceinline__ uint32_t smem_u32(const void* p) {
    uint32_t a;
    asm("{ .reg .u64 t; cvta.to.shared.u64 t, %1; cvt.u32.u64 %0, t; }" : "=r"(a) : "l"(p));
    return a;
}
__device__ __forceinline__ float tanh_fast(float x) {
    float r; asm("tanh.approx.f32 %0, %1;" : "=f"(r) : "f"(x)); return r;
}
__device__ __forceinline__ uint32_t pack_bf16x2(float lo, float hi) {
    uint32_t r; asm("cvt.rn.bf16x2.f32 %0, %1, %2;" : "=r"(r) : "f"(hi), "f"(lo)); return r;
}
__device__ __forceinline__ void cp_async16(uint32_t dst, const void* src) {
    asm volatile("cp.async.cg.shared.global [%0], [%1], 16;\n" :: "r"(dst), "l"(src) : "memory");
}
__device__ __forceinline__ void ldsm_x4(uint32_t (&r)[4], uint32_t addr) {
    asm volatile("ldmatrix.sync.aligned.m8n8.x4.shared.b16 {%0,%1,%2,%3}, [%4];"
                 : "=r"(r[0]), "=r"(r[1]), "=r"(r[2]), "=r"(r[3]) : "r"(addr));
}
__device__ __forceinline__ void mma_bf16(float (&c)[4], const uint32_t (&a)[4],
                                         uint32_t b0, uint32_t b1) {
    asm volatile(
        "mma.sync.aligned.m16n8k16.row.col.f32.bf16.bf16.f32 "
        "{%0,%1,%2,%3}, {%4,%5,%6,%7}, {%8,%9}, {%0,%1,%2,%3};"
        : "+f"(c[0]), "+f"(c[1]), "+f"(c[2]), "+f"(c[3])
        : "r"(a[0]), "r"(a[1]), "r"(a[2]), "r"(a[3]), "r"(b0), "r"(b1));
}

// =====================================================================
// K1: prep — fused W_proj convert + enc/dec projections (one launch)
// gemm tiles 32m x 64n: enc 32mt x 8nt = 256 blocks, dec 9 x 8 = 72
// blocks [328, 328+2048): W_proj fp32->bf16 convert
// =====================================================================
#define PREP_ENC_BLOCKS 256
#define PREP_GEMM_BLOCKS 328
#define PREP_BLOCKS (PREP_GEMM_BLOCKS + (VV*DJ)/256)

__global__ void __launch_bounds__(128) prep_kernel(
    const float* __restrict__ enc, const float* __restrict__ Wenc,
    const float* __restrict__ benc,
    const float* __restrict__ dec, const float* __restrict__ Wdec,
    const float* __restrict__ bdec,
    const float* __restrict__ Wp, const int* __restrict__ in_len)
{
    const int bid = blockIdx.x;
    const int tid = threadIdx.x;

    if (bid >= PREP_GEMM_BLOCKS) {
        int idx = (bid - PREP_GEMM_BLOCKS) * 256 + tid * 2;
        float2 v = *reinterpret_cast<const float2*>(&Wp[idx]);
        *reinterpret_cast<uint32_t*>(&g_wp[idx]) = pack_bf16x2(v.x, v.y);
        return;
    }

    const float* A; const float* W; const float* bias; float* C; int M;
    int mt, nt;
    if (bid < PREP_ENC_BLOCKS) {
        A = enc; W = Wenc; bias = benc; M = BB * TT;
        C = g_enc_h;
        mt = bid >> 3; nt = bid & 7;
        // dead-row skip: rows m0..m0+31 share batch b (8 tiles/batch)
        int m0 = mt * 32;
        int b = m0 >> 8, t_min = m0 & 255;
        if (t_min >= in_len[b]) return;
    } else {
        A = dec; W = Wdec; bias = bdec; M = BB * UP;
        C = g_dec_h;
        int lb = bid - PREP_ENC_BLOCKS;
        mt = lb >> 3; nt = lb & 7;
    }
    const int m0 = mt * 32;
    const int n0 = nt * 64;
    const int K = 512;

    __shared__ float As[16][36];   // stride 144B (16B-multiple)
    __shared__ float Ws[16][72];   // stride 288B
    const int ty = tid >> 4;        // 0..7  -> 4 rows each (32 rows)
    const int tx = tid & 15;        // 0..15 -> 4 cols each (64 cols)
    const int arow = tid >> 2;      // 0..31
    const int ak   = (tid & 3) * 4; // 0,4,8,12
    const int wrow = tid >> 1;      // 0..63
    const int wk   = (tid & 1) * 8; // 0 or 8

    float acc[4][4];
#pragma unroll
    for (int i = 0; i < 4; i++)
#pragma unroll
        for (int j = 0; j < 4; j++) acc[i][j] = 0.f;

    for (int k0 = 0; k0 < K; k0 += 16) {
        const int gm = m0 + arow;
        float4 a0;
        if (gm < M) a0 = *reinterpret_cast<const float4*>(&A[(size_t)gm * K + k0 + ak]);
        else        a0 = make_float4(0.f, 0.f, 0.f, 0.f);
        const int gn = n0 + wrow;   // N=512, always valid
        float4 w0 = *reinterpret_cast<const float4*>(&W[(size_t)gn * K + k0 + wk]);
        float4 w1 = *reinterpret_cast<const float4*>(&W[(size_t)gn * K + k0 + wk + 4]);
        __syncthreads();
        As[ak + 0][arow] = a0.x; As[ak + 1][arow] = a0.y;
        As[ak + 2][arow] = a0.z; As[ak + 3][arow] = a0.w;
        Ws[wk + 0][wrow] = w0.x; Ws[wk + 1][wrow] = w0.y;
        Ws[wk + 2][wrow] = w0.z; Ws[wk + 3][wrow] = w0.w;
        Ws[wk + 4][wrow] = w1.x; Ws[wk + 5][wrow] = w1.y;
        Ws[wk + 6][wrow] = w1.z; Ws[wk + 7][wrow] = w1.w;
        __syncthreads();
#pragma unroll
        for (int kk = 0; kk < 16; kk++) {
            float4 av = *reinterpret_cast<const float4*>(&As[kk][ty * 4]);
            float4 wv = *reinterpret_cast<const float4*>(&Ws[kk][tx * 4]);
            float a[4] = {av.x, av.y, av.z, av.w};
            float w[4] = {wv.x, wv.y, wv.z, wv.w};
#pragma unroll
            for (int i = 0; i < 4; i++)
#pragma unroll
                for (int j = 0; j < 4; j++)
                    acc[i][j] = fmaf(a[i], w[j], acc[i][j]);
        }
    }

    float4 bv = *reinterpret_cast<const float4*>(&bias[n0 + tx * 4]);
#pragma unroll
    for (int i = 0; i < 4; i++) {
        int gm = m0 + ty * 4 + i;
        if (gm < M) {
            float4 o;
            o.x = acc[i][0] + bv.x; o.y = acc[i][1] + bv.y;
            o.z = acc[i][2] + bv.z; o.w = acc[i][3] + bv.w;
            *reinterpret_cast<float4*>(&C[(size_t)gm * DJ + n0 + tx * 4]) = o;
        }
    }
}

// =====================================================================
// K3: mma.sync bf16 joint GEMM + fused log-softmax + dead-tile skip
// =====================================================================
__device__ __forceinline__ void load_b_tile(int bt, uint32_t b_base, int tid) {
    uint32_t buf = b_base + (uint32_t)(bt % NBUF) * BT_BYTES;
    const int nc = bt >> 3, ktl = bt & 7;
    const int n = tid >> 1;                 // 256 rows, 2 threads/row
    const int c0 = (tid & 1) * 4;           // 4 x 16B per thread
    const __nv_bfloat16* src = g_wp + ((size_t)(nc * 256 + n) * DJ + ktl * 64 + c0 * 8);
    const uint32_t row = buf + (uint32_t)n * 128u;
    const uint32_t sw = (uint32_t)(n & 7);
#pragma unroll
    for (int j = 0; j < 4; j++) {
        uint32_t c = (uint32_t)(c0 + j);
        cp_async16(row + ((c ^ sw) << 4), src + j * 8);
    }
    asm volatile("cp.async.commit_group;" ::: "memory");
}

__global__ void __launch_bounds__(JTHREADS, 1) joint_kernel(
    const int* __restrict__ targets, const int* __restrict__ in_len)
{
    extern __shared__ __align__(16) char dyn[];
    __shared__ int tgtm[MTILE];

    const int g0 = blockIdx.x * MTILE;
    {   // dead-tile early exit (uniform across CTA, before any barrier)
        int b = g0 / (TT * UP);
        int t_min = (g0 - b * (TT * UP)) / UP;
        if (t_min >= in_len[b]) return;
    }

    const uint32_t base = (smem_u32(dyn) + 1023u) & ~1023u;
    const uint32_t a_base = base;
    const uint32_t b_base = base + A_BYTES;

    const int tid  = threadIdx.x;
    const int lane = tid & 31;
    const int wid  = tid >> 5;
    const int warp_m = wid & 3;     // 4 M-warps of 32 rows
    const int warp_n = wid >> 2;    // 4 N-warps of 64 cols (over 256-col chunk)
    const unsigned FM = 0xffffffffu;

    if (tid < MTILE) {
        int g = g0 + tid;
        int b = g / (TT * UP);
        int r = g - b * (TT * UP);
        int u = r % UP;
        tgtm[tid] = (u < UU) ? targets[b * UU + u] : -1;
    }

    // ---- generate h tile into XOR-swizzled A (bf16); each thread 128 k ----
    {
        const int m = tid >> 2;
        const int kq = (tid & 3) * 128;
        int g = g0 + m;
        int b = g / (TT * UP);
        int r = g - b * (TT * UP);
        int t = r / UP, u = r - t * UP;
        const float4* er = reinterpret_cast<const float4*>(
            g_enc_h + ((size_t)(b * TT + t)) * DJ + kq);
        const float4* dr = reinterpret_cast<const float4*>(
            g_dec_h + ((size_t)(b * UP + u)) * DJ + kq);
        const uint32_t mrow = a_base + (uint32_t)m * 1024u;
        const uint32_t msw = (uint32_t)(m & 7);
#pragma unroll 4
        for (int i = 0; i < 16; i++) {
            int k = kq + i * 8;
            float4 e0 = er[i * 2], e1 = er[i * 2 + 1];
            float4 d0 = dr[i * 2], d1 = dr[i * 2 + 1];
            uint32_t p0 = pack_bf16x2(tanh_fast(e0.x * d0.x), tanh_fast(e0.y * d0.y));
            uint32_t p1 = pack_bf16x2(tanh_fast(e0.z * d0.z), tanh_fast(e0.w * d0.w));
            uint32_t p2 = pack_bf16x2(tanh_fast(e1.x * d1.x), tanh_fast(e1.y * d1.y));
            uint32_t p3 = pack_bf16x2(tanh_fast(e1.z * d1.z), tanh_fast(e1.w * d1.w));
            uint32_t c = (uint32_t)(k >> 3);
            uint32_t addr = mrow + ((c ^ msw) << 4);
            asm volatile("st.shared.v4.b32 [%0], {%1,%2,%3,%4};"
                         :: "r"(addr), "r"(p0), "r"(p1), "r"(p2), "r"(p3) : "memory");
        }
    }
    __syncthreads();

    // ---- prologue: prefetch B tiles 0,1 ----
    load_b_tile(0, b_base, tid);
    load_b_tile(1, b_base, tid);

    // ---- per-lane ldmatrix addressing ----
    const int rowA = warp_m * 32 + (lane & 15);
    const uint32_t a_lane = a_base + (uint32_t)rowA * 1024u;
    const uint32_t swzA = (uint32_t)(rowA & 7);
    const uint32_t cbaseA = (uint32_t)(lane >> 4);
    const int n_row_base = warp_n * 64 + ((lane >> 4) << 3) + (lane & 7);
    const uint32_t kh = (uint32_t)((lane >> 3) & 1);
    const uint32_t swzB = (uint32_t)(lane & 7);
    uint32_t rowoffB[4];
#pragma unroll
    for (int p = 0; p < 4; p++) rowoffB[p] = (uint32_t)(n_row_base + p * 16) * 128u;

    // ---- per-row epilogue state ----
    float sm[4], blankv[4], tgtv[4];
    int tg[4];
#pragma unroll
    for (int g = 0; g < 4; g++) {
        sm[g] = 0.f; blankv[g] = 0.f; tgtv[g] = 0.f;
        int m = warp_m * 32 + (g >> 1) * 16 + (g & 1) * 8 + (lane >> 2);
        tg[g] = tgtm[m];
    }

    float acc[2][8][4];

#pragma unroll 1
    for (int bt = 0; bt < NTILES; bt++) {
        const int ktl = bt & 7;
        if (bt < NTILES - 1) asm volatile("cp.async.wait_group 1;" ::: "memory");
        else                 asm volatile("cp.async.wait_group 0;" ::: "memory");
        __syncthreads();
        if (bt + 2 < NTILES) load_b_tile(bt + 2, b_base, tid);

        if (ktl == 0) {
#pragma unroll
            for (int mi = 0; mi < 2; mi++)
#pragma unroll
                for (int nf = 0; nf < 8; nf++)
#pragma unroll
                    for (int j = 0; j < 4; j++) acc[mi][nf][j] = 0.f;
        }

        const uint32_t bbuf = b_base + (uint32_t)(bt % NBUF) * BT_BYTES;
#pragma unroll
        for (int s = 0; s < 4; s++) {
            uint32_t a0[4], a1[4];
            uint32_t cA = (uint32_t)(ktl * 8 + s * 2) + cbaseA;
            uint32_t aaddr = a_lane + ((cA ^ swzA) << 4);
            ldsm_x4(a0, aaddr);
            ldsm_x4(a1, aaddr + 16384u);
            uint32_t b[4][4];
            uint32_t cB = ((uint32_t)(s * 2) + kh) ^ swzB;
#pragma unroll
            for (int p = 0; p < 4; p++)
                ldsm_x4(b[p], bbuf + rowoffB[p] + (cB << 4));
#pragma unroll
            for (int p = 0; p < 4; p++) {
                mma_bf16(acc[0][2 * p],     a0, b[p][0], b[p][1]);
                mma_bf16(acc[0][2 * p + 1], a0, b[p][2], b[p][3]);
                mma_bf16(acc[1][2 * p],     a1, b[p][0], b[p][1]);
                mma_bf16(acc[1][2 * p + 1], a1, b[p][2], b[p][3]);
            }
        }

        if (ktl == 7) {
            const int nc = bt >> 3;
            const int vbase = nc * 256 + warp_n * 64 + (lane & 3) * 2;
#pragma unroll
            for (int g = 0; g < 4; g++) {
                const int mi = g >> 1, hf = (g & 1) * 2;
                float ls = 0.f;
#pragma unroll
                for (int nf = 0; nf < 8; nf++)
                    ls += __expf(acc[mi][nf][hf]) + __expf(acc[mi][nf][hf + 1]);
                ls += __shfl_xor_sync(FM, ls, 1);
                ls += __shfl_xor_sync(FM, ls, 2);
                sm[g] += ls;
#pragma unroll
                for (int nf = 0; nf < 8; nf++) {
                    int v0 = vbase + nf * 8;
                    if (v0 == 0)         blankv[g] = acc[mi][nf][hf];
                    if (v0 == tg[g])     tgtv[g]   = acc[mi][nf][hf];
                    if (v0 + 1 == tg[g]) tgtv[g]   = acc[mi][nf][hf + 1];
                }
            }
        }
    }

    // gather captured values across the 4 lanes of each row group
#pragma unroll
    for (int g = 0; g < 4; g++) {
        tgtv[g]   += __shfl_xor_sync(FM, tgtv[g], 1);
        tgtv[g]   += __shfl_xor_sync(FM, tgtv[g], 2);
        blankv[g] += __shfl_xor_sync(FM, blankv[g], 1);
        blankv[g] += __shfl_xor_sync(FM, blankv[g], 2);
    }

    // reuse B buffer smem for the cross-n-warp combine
    __syncthreads();
    float* ssum   = reinterpret_cast<float*>(dyn) + ((b_base - smem_u32(dyn)) >> 2);
    float* stgtv  = ssum + 4 * MTILE;
    float* sblank = stgtv + 4 * MTILE;

    if ((lane & 3) == 0) {
#pragma unroll
        for (int g = 0; g < 4; g++) {
            int m = warp_m * 32 + (g >> 1) * 16 + (g & 1) * 8 + (lane >> 2);
            ssum[warp_n * MTILE + m]  = sm[g];
            stgtv[warp_n * MTILE + m] = tgtv[g];
            if (warp_n == 0) sblank[m] = blankv[g];
        }
    }
    __syncthreads();

    if (tid < MTILE) {
        int m = tid;
        float lse = __logf(ssum[m] + ssum[MTILE + m] + ssum[2 * MTILE + m] + ssum[3 * MTILE + m]);
        int g = g0 + m;
        int b = g / (TT * UP);
        int r = g - b * (TT * UP);
        int t = r / UP, u = r - t * UP;
        g_blank[g] = sblank[m] - lse;
        if (u < UU) {
            int h = (tgtm[m] >> 6) & 3;   // which 64-col N-warp owns target
            g_emit[(size_t)(b * TT + t) * UU + u] = stgtv[h * MTILE + m] - lse;
        }
    }
}

// =====================================================================
// K4: alpha DP — branchless anti-diagonal wavefront + fused finalize
// =====================================================================
__device__ __forceinline__ float lse2(float a, float b) {
    float m = fmaxf(a, b);
    float n = fminf(a, b);
    return m + __logf(1.f + __expf(n - m));
}

#define DP_PAD0 4096
#define DP_BL_FLOATS (TT*UP)             // 16640
#define DP_EM_FLOATS (TT*UU)             // 16384
#define DP_PAD1 4224
#define DP_TOT (DP_PAD0 + DP_BL_FLOATS + DP_EM_FLOATS + DP_PAD1)
#define DP_SMEM_BYTES (DP_TOT * 4)       // 165376

__global__ void __launch_bounds__(256, 1) dp_kernel(
    const int* __restrict__ in_len, const int* __restrict__ tgt_len,
    float* __restrict__ out)
{
    extern __shared__ float sdp[];
    float* sbl = sdp + DP_PAD0;
    float* sem = sbl + DP_BL_FLOATS;

    const int b = blockIdx.x;
    const int tid = threadIdx.x;

    {
        float4 z = make_float4(0.f, 0.f, 0.f, 0.f);
        float4* gp0 = reinterpret_cast<float4*>(sdp);
        for (int q = tid; q < DP_PAD0 / 4; q += 256) gp0[q] = z;
        float4* gp1 = reinterpret_cast<float4*>(sem + DP_EM_FLOATS);
        for (int q = tid; q < DP_PAD1 / 4; q += 256) gp1[q] = z;
    }
    {
        const float4* gb = reinterpret_cast<const float4*>(g_blank + (size_t)b * DP_BL_FLOATS);
        float4* sb = reinterpret_cast<float4*>(sbl);
#pragma unroll
        for (int i = 0; i < DP_BL_FLOATS / 4 / 256 + 1; i++) {
            int q = tid + i * 256;
            if (q < DP_BL_FLOATS / 4) sb[q] = gb[q];
        }
        const float4* ge = reinterpret_cast<const float4*>(g_emit + (size_t)b * DP_EM_FLOATS);
        float4* se = reinterpret_cast<float4*>(sem);
#pragma unroll
        for (int i = 0; i < DP_EM_FLOATS / 4 / 256; i++) {
            int q = tid + i * 256;
            se[q] = ge[q];
        }
    }
    __syncthreads();

    if (tid >= 32) return;
    const int lane = tid;
    const int til = in_len[b];
    const int ul  = tgt_len[b];
    const int dmax = til - 1 + ul;
    const float NEG = -1e30f;
    const unsigned FM = 0xffffffffu;

    int u[3], uc[3];
    float al[3];
#pragma unroll
    for (int j = 0; j < 3; j++) {
        u[j] = lane * 3 + j;
        uc[j] = (u[j] > UU) ? UU : u[j];
        al[j] = (u[j] == 0) ? 0.f : NEG;
    }

    int ibl[3], iem[3];
#pragma unroll
    for (int j = 0; j < 3; j++) {
        ibl[j] = -UU * uc[j];
        iem[j] = (UU - 1) - (UU - 1) * uc[j];
    }

    float bl[3], em[3];
#pragma unroll
    for (int j = 0; j < 3; j++) { bl[j] = sbl[ibl[j]]; em[j] = sem[iem[j]]; }

#pragma unroll 2
    for (int d = 1; d <= dmax; d++) {
        float nbl[3], nem[3];
#pragma unroll
        for (int j = 0; j < 3; j++) {
            ibl[j] += UP; iem[j] += UU;
            nbl[j] = sbl[ibl[j]];
            nem[j] = sem[iem[j]];
        }

        float nb0 = __shfl_up_sync(FM, al[2], 1);
        if (lane == 0) nb0 = NEG;

        float nw0 = lse2(al[0] + bl[0], nb0   + em[0]);
        float nw1 = lse2(al[1] + bl[1], al[0] + em[1]);
        float nw2 = lse2(al[2] + bl[2], al[1] + em[2]);
        al[0] = nw0; al[1] = nw1; al[2] = nw2;

        bl[0] = nbl[0]; bl[1] = nbl[1]; bl[2] = nbl[2];
        em[0] = nem[0]; em[1] = nem[1]; em[2] = nem[2];
    }

#pragma unroll
    for (int j = 0; j < 3; j++) {
        if (u[j] == ul)
            atomicAdd(out, -0.25f * (al[j] + sbl[(til - 1) * UP + ul]));
    }
}

// =====================================================================
// launch
// =====================================================================
extern "C" void kernel_launch(void* const* d_in, const int* in_sizes, int n_in,
                              void* d_out, int out_size)
{
    const float* enc     = (const float*)d_in[0];
    const float* dec     = (const float*)d_in[1];
    const int*   targets = (const int*)  d_in[2];
    const int*   in_len  = (const int*)  d_in[3];
    const int*   tgt_len = (const int*)  d_in[4];
    const float* W_enc   = (const float*)d_in[5];
    const float* b_enc   = (const float*)d_in[6];
    const float* W_dec   = (const float*)d_in[7];
    const float* b_dec   = (const float*)d_in[8];
    const float* W_proj  = (const float*)d_in[9];

    const int smem_joint = 1024 + A_BYTES + NBUF * BT_BYTES;   // 230400 B
    cudaFuncSetAttribute(joint_kernel, cudaFuncAttributeMaxDynamicSharedMemorySize, smem_joint);
    cudaFuncSetAttribute(dp_kernel, cudaFuncAttributeMaxDynamicSharedMemorySize, DP_SMEM_BYTES);

    cudaMemsetAsync(d_out, 0, sizeof(float));

    prep_kernel<<<PREP_BLOCKS, 128>>>(enc, W_enc, b_enc,
                                      dec, W_dec, b_dec,
                                      W_proj, in_len);

    joint_kernel<<<(BB * TT * UP) / MTILE, JTHREADS, smem_joint>>>(targets, in_len);

    dp_kernel<<<BB, 256, DP_SMEM_BYTES>>>(in_len, tgt_len, (float*)d_out);
}